// round 2
// baseline (speedup 1.0000x reference)
#include <cuda_runtime.h>
#include <math.h>

#define Bz 8
#define Dd 1024
#define Ll 2048

// exp(0.01)
#define CAUCHY_E 1.0100501670841680575f

// ---------------------------------------------------------------------------
// Scratch (allocation-free: __device__ globals)
// ---------------------------------------------------------------------------
__device__ float g_t1[(size_t)Bz * Dd * Ll];      // 64 MB ping
__device__ float g_t2[(size_t)Bz * Dd * Ll];      // 64 MB pong
__device__ float g_sx[(size_t)Bz * Dd * Ll];      // 64 MB
__device__ float g_cx[(size_t)Bz * Dd * Ll];      // 64 MB
__device__ float g_dscore[(size_t)Bz * Dd * Dd];  // 32 MB
__device__ float g_lscore[(size_t)Bz * Ll * Ll];  // 128 MB
__device__ float g_ss[(size_t)Bz * Ll];
__device__ float g_cs[(size_t)Bz * Ll];

// ---------------------------------------------------------------------------
// Generic SGEMM: C[b] = op(A[b]) * op(B[b]) (+ epilogue)
//   TA=0: A is M x K (lda = row stride);  TA=1: A is K x M
//   TB=0: B is K x N;                     TB=1: B is N x K
//   EPI=0: C = acc
//   EPI=1: C = acc + aux[m]              (per-row bias)
//   EPI=2: C = (acc + aux[b,m,n]) * 0.5  (residual average)
// Block tile 128x128, K-step 8, 256 threads, 8x8 per thread.
// Requires M,N % 128 == 0, K % 8 == 0, all leading dims % 4 == 0.
// ---------------------------------------------------------------------------
template <int TA, int TB, int EPI>
__global__ void __launch_bounds__(256, 2) gemm_kernel(
    int M, int N, int K,
    const float* __restrict__ A, int lda, long strideA,
    const float* __restrict__ B, int ldb, long strideB,
    float* __restrict__ C, int ldc, long strideC,
    const float* __restrict__ aux, long strideAux)
{
    __shared__ float As[8][128];
    __shared__ float Bs[8][132];   // +4 pad; row stride 132 floats = 16B aligned

    const int tid = threadIdx.x;
    const int tx = tid & 15;       // n direction
    const int ty = tid >> 4;       // m direction
    const int m0 = blockIdx.y * 128;
    const int n0 = blockIdx.x * 128;
    const int bz = blockIdx.z;

    A += (long)bz * strideA;
    B += (long)bz * strideB;
    C += (long)bz * strideC;

    float acc[8][8];
#pragma unroll
    for (int i = 0; i < 8; i++)
#pragma unroll
        for (int j = 0; j < 8; j++) acc[i][j] = 0.f;

    for (int k0 = 0; k0 < K; k0 += 8) {
        // ---- load A tile into As[k][m] ----
        if (!TA) {
            int r = tid >> 1;             // 0..127 (m)
            int c = (tid & 1) * 4;        // 0 or 4 (k)
            float4 v = *(const float4*)&A[(long)(m0 + r) * lda + k0 + c];
            As[c + 0][r] = v.x; As[c + 1][r] = v.y;
            As[c + 2][r] = v.z; As[c + 3][r] = v.w;
        } else {
            int r = tid >> 5;             // 0..7  (k)
            int c = (tid & 31) * 4;       // 0..124 (m)
            float4 v = *(const float4*)&A[(long)(k0 + r) * lda + m0 + c];
            *(float4*)&As[r][c] = v;
        }
        // ---- load B tile into Bs[k][n] ----
        if (!TB) {
            int r = tid >> 5;             // k
            int c = (tid & 31) * 4;       // n
            float4 v = *(const float4*)&B[(long)(k0 + r) * ldb + n0 + c];
            *(float4*)&Bs[r][c] = v;
        } else {
            int r = tid >> 1;             // n
            int c = (tid & 1) * 4;        // k
            float4 v = *(const float4*)&B[(long)(n0 + r) * ldb + k0 + c];
            Bs[c + 0][r] = v.x; Bs[c + 1][r] = v.y;
            Bs[c + 2][r] = v.z; Bs[c + 3][r] = v.w;
        }
        __syncthreads();

#pragma unroll
        for (int kk = 0; kk < 8; kk++) {
            float a[8], b[8];
            *(float4*)&a[0] = *(const float4*)&As[kk][ty * 8];
            *(float4*)&a[4] = *(const float4*)&As[kk][ty * 8 + 4];
            *(float4*)&b[0] = *(const float4*)&Bs[kk][tx * 8];
            *(float4*)&b[4] = *(const float4*)&Bs[kk][tx * 8 + 4];
#pragma unroll
            for (int i = 0; i < 8; i++)
#pragma unroll
                for (int j = 0; j < 8; j++)
                    acc[i][j] = fmaf(a[i], b[j], acc[i][j]);
        }
        __syncthreads();
    }

    // ---- epilogue ----
#pragma unroll
    for (int i = 0; i < 8; i++) {
        int m = m0 + ty * 8 + i;
        float bias = 0.f;
        if (EPI == 1) bias = aux[m];
#pragma unroll
        for (int j = 0; j < 8; j += 4) {
            int n = n0 + tx * 8 + j;
            float4 r;
            r.x = acc[i][j + 0]; r.y = acc[i][j + 1];
            r.z = acc[i][j + 2]; r.w = acc[i][j + 3];
            if (EPI == 1) { r.x += bias; r.y += bias; r.z += bias; r.w += bias; }
            if (EPI == 2) {
                float4 xres = *(const float4*)&aux[(long)bz * strideAux + (long)m * ldc + n];
                r.x = (r.x + xres.x) * 0.5f; r.y = (r.y + xres.y) * 0.5f;
                r.z = (r.z + xres.z) * 0.5f; r.w = (r.w + xres.w) * 0.5f;
            }
            *(float4*)&C[(long)m * ldc + n] = r;
        }
    }
}

// ---------------------------------------------------------------------------
// Reductions & pointwise
// ---------------------------------------------------------------------------
__device__ __forceinline__ float blockReduceSum(float v) {
    __shared__ float sm[32];
    __syncthreads();
    int lane = threadIdx.x & 31, w = threadIdx.x >> 5;
#pragma unroll
    for (int o = 16; o; o >>= 1) v += __shfl_down_sync(0xffffffffu, v, o);
    if (!lane) sm[w] = v;
    __syncthreads();
    int nw = blockDim.x >> 5;
    v = (threadIdx.x < nw) ? sm[threadIdx.x] : 0.f;
    if (w == 0) {
#pragma unroll
        for (int o = 16; o; o >>= 1) v += __shfl_down_sync(0xffffffffu, v, o);
        if (!lane) sm[0] = v;
    }
    __syncthreads();
    return sm[0];
}

__device__ __forceinline__ float blockReduceMax(float v) {
    __shared__ float sm[32];
    __syncthreads();
    int lane = threadIdx.x & 31, w = threadIdx.x >> 5;
#pragma unroll
    for (int o = 16; o; o >>= 1) v = fmaxf(v, __shfl_down_sync(0xffffffffu, v, o));
    if (!lane) sm[w] = v;
    __syncthreads();
    int nw = blockDim.x >> 5;
    v = (threadIdx.x < nw) ? sm[threadIdx.x] : -1e30f;
    if (w == 0) {
#pragma unroll
        for (int o = 16; o; o >>= 1) v = fmaxf(v, __shfl_down_sync(0xffffffffu, v, o));
        if (!lane) sm[0] = v;
    }
    __syncthreads();
    return sm[0];
}

// out[row] = sum over contiguous Lc of X[row,:]^2   (one block per row)
__global__ void rowsq_kernel(const float* __restrict__ X, float* __restrict__ out, int Lc) {
    long row = blockIdx.x;
    const float* p = X + row * (long)Lc;
    float s = 0.f;
    for (int i = threadIdx.x * 4; i < Lc; i += blockDim.x * 4) {
        float4 v = *(const float4*)&p[i];
        s += v.x * v.x + v.y * v.y + v.z * v.z + v.w * v.w;
    }
    s = blockReduceSum(s);
    if (threadIdx.x == 0) out[row] = s;
}

// out[b*Ln + l] = sum_d X[b,d,l]^2   (thread per (b,l), strided-but-coalesced)
__global__ void colsq_kernel(const float* __restrict__ X, float* __restrict__ out, int Dn, int Ln) {
    int l = blockIdx.x * blockDim.x + threadIdx.x;
    int b = blockIdx.z;
    const float* p = X + (long)b * Dn * Ln + l;
    float s = 0.f;
    for (int d = 0; d < Dn; d++) {
        float v = p[(long)d * Ln];
        s = fmaf(v, v, s);
    }
    out[(long)b * Ln + l] = s;
}

// In-place: S = relu(0.5 - 0.5*cos(pi*((S^2/(ss[m]*cs[n]))^e - eye)))
__global__ void cauchy_kernel(float* __restrict__ S,
                              const float* __restrict__ ss,
                              const float* __restrict__ cs, int M) {
    long idx = (long)blockIdx.x * blockDim.x + threadIdx.x;
    long total = (long)Bz * M * M;
    if (idx >= total) return;
    int c = (int)(idx % M);
    int r = (int)((idx / M) % M);
    int b = (int)(idx / ((long)M * M));
    float mm = S[idx];
    float v = (mm * mm) / (ss[(long)b * M + r] * cs[(long)b * M + c]);
    float p = powf(v, CAUCHY_E);
    if (r == c) p -= 1.0f;
    float o = 0.5f - 0.5f * cospif(p);
    S[idx] = fmaxf(o, 0.0f);
}

// softmax over axis 1 of (B, M, M): per (b, n) column. Thread per column.
__global__ void softmax_col_kernel(float* __restrict__ S, int M) {
    int n = blockIdx.x * blockDim.x + threadIdx.x;
    int b = blockIdx.z;
    float* base = S + (long)b * M * M + n;
    float mx = -1e30f;
    for (int m = 0; m < M; m++) mx = fmaxf(mx, base[(long)m * M]);
    float s = 0.f;
    for (int m = 0; m < M; m++) {
        float e = expf(base[(long)m * M] - mx);
        base[(long)m * M] = e;
        s += e;
    }
    float inv = 1.0f / s;
    for (int m = 0; m < M; m++) base[(long)m * M] *= inv;
}

// softmax over last axis, one block per row of length n
__global__ void softmax_row_kernel(float* __restrict__ S, int n) {
    float* p = S + (long)blockIdx.x * n;
    float mx = -1e30f;
    for (int i = threadIdx.x; i < n; i += blockDim.x) mx = fmaxf(mx, p[i]);
    mx = blockReduceMax(mx);
    float s = 0.f;
    for (int i = threadIdx.x; i < n; i += blockDim.x) {
        float e = expf(p[i] - mx);
        p[i] = e;
        s += e;
    }
    s = blockReduceSum(s);
    float inv = 1.0f / s;
    for (int i = threadIdx.x; i < n; i += blockDim.x) p[i] *= inv;
}

// ---------------------------------------------------------------------------
// Orchestration
// ---------------------------------------------------------------------------
extern "C" void kernel_launch(void* const* d_in, const int* in_sizes, int n_in,
                              void* d_out, int out_size) {
    (void)in_sizes; (void)n_in; (void)out_size;
    const float* x = (const float*)d_in[0];
    const float* W[4] = {(const float*)d_in[1], (const float*)d_in[3],
                         (const float*)d_in[5], (const float*)d_in[7]};
    const float* bv[4] = {(const float*)d_in[2], (const float*)d_in[4],
                          (const float*)d_in[6], (const float*)d_in[8]};
    float* out = (float*)d_out;

    float *t1, *t2, *sx, *cx, *dsc, *lsc, *ss, *cs;
    cudaGetSymbolAddress((void**)&t1,  g_t1);
    cudaGetSymbolAddress((void**)&t2,  g_t2);
    cudaGetSymbolAddress((void**)&sx,  g_sx);
    cudaGetSymbolAddress((void**)&cx,  g_cx);
    cudaGetSymbolAddress((void**)&dsc, g_dscore);
    cudaGetSymbolAddress((void**)&lsc, g_lscore);
    cudaGetSymbolAddress((void**)&ss,  g_ss);
    cudaGetSymbolAddress((void**)&cs,  g_cs);

    const long sXDL = (long)Dd * Ll;
    const dim3 blk(256);
    const dim3 gMLP(Ll / 128, Dd / 128, Bz);

    // 3-layer pointwise MLP: dst = L3(L2(L1(x)))
    auto mlp = [&](const float* Wi, const float* bi, float* dst) {
        gemm_kernel<0, 0, 1><<<gMLP, blk>>>(Dd, Ll, Dd,
            Wi, Dd, 0, x, Ll, sXDL, t1, Ll, sXDL, bi, 0);
        gemm_kernel<0, 0, 1><<<gMLP, blk>>>(Dd, Ll, Dd,
            Wi + (long)Dd * Dd, Dd, 0, t1, Ll, sXDL, t2, Ll, sXDL, bi + Dd, 0);
        gemm_kernel<0, 0, 1><<<gMLP, blk>>>(Dd, Ll, Dd,
            Wi + 2L * Dd * Dd, Dd, 0, t2, Ll, sXDL, dst, Ll, sXDL, bi + 2 * Dd, 0);
    };

    // ---------------- dscore branch ----------------
    mlp(W[0], bv[0], sx);   // dsx
    mlp(W[1], bv[1], cx);   // dcx
    rowsq_kernel<<<Bz * Dd, 256>>>(sx, ss, Ll);
    rowsq_kernel<<<Bz * Dd, 256>>>(cx, cs, Ll);
    // dnum = dsx @ dcx^T : NT, (D x D), K = L
    gemm_kernel<0, 1, 0><<<dim3(Dd / 128, Dd / 128, Bz), blk>>>(Dd, Dd, Ll,
        sx, Ll, sXDL, cx, Ll, sXDL, dsc, Dd, (long)Dd * Dd, nullptr, 0);
    {
        long total = (long)Bz * Dd * Dd;
        cauchy_kernel<<<(unsigned)((total + 255) / 256), 256>>>(dsc, ss, cs, Dd);
    }
    softmax_col_kernel<<<dim3(Dd / 256, 1, Bz), 256>>>(dsc, Dd);

    // ---------------- lscore branch ----------------
    mlp(W[2], bv[2], sx);   // lsx
    mlp(W[3], bv[3], cx);   // lcx
    colsq_kernel<<<dim3(Ll / 256, 1, Bz), 256>>>(sx, ss, Dd, Ll);
    colsq_kernel<<<dim3(Ll / 256, 1, Bz), 256>>>(cx, cs, Dd, Ll);
    // lnum = lsx^T @ lcx : TN, (L x L), K = D
    gemm_kernel<1, 0, 0><<<dim3(Ll / 128, Ll / 128, Bz), blk>>>(Ll, Ll, Dd,
        sx, Ll, sXDL, cx, Ll, sXDL, lsc, Ll, (long)Ll * Ll, nullptr, 0);
    {
        long total = (long)Bz * Ll * Ll;
        cauchy_kernel<<<(unsigned)((total + 255) / 256), 256>>>(lsc, ss, cs, Ll);
    }
    softmax_row_kernel<<<Bz * Ll, 256>>>(lsc, Ll);

    // ---------------- combine ----------------
    // T = dscore @ x  (D x L, K = D)
    gemm_kernel<0, 0, 0><<<gMLP, blk>>>(Dd, Ll, Dd,
        dsc, Dd, (long)Dd * Dd, x, Ll, sXDL, t1, Ll, sXDL, nullptr, 0);
    // out = (T @ lscore + x) / 2  (D x L, K = L)
    gemm_kernel<0, 0, 2><<<gMLP, blk>>>(Dd, Ll, Ll,
        t1, Ll, sXDL, lsc, Ll, (long)Ll * Ll, out, Ll, sXDL, x, sXDL);
}

// round 4
// speedup vs baseline: 1.0014x; 1.0014x over previous
#include <cuda_runtime.h>
#include <math.h>

#define Bz 8
#define Dd 1024
#define Ll 2048

// exp(0.01)
#define CAUCHY_E 1.0100501670841680575f

// ---------------------------------------------------------------------------
// Scratch (allocation-free: __device__ globals)
// ---------------------------------------------------------------------------
__device__ float g_t1[(size_t)Bz * Dd * Ll];      // 64 MB ping
__device__ float g_t2[(size_t)Bz * Dd * Ll];      // 64 MB pong
__device__ float g_sx[(size_t)Bz * Dd * Ll];      // 64 MB
__device__ float g_cx[(size_t)Bz * Dd * Ll];      // 64 MB
__device__ float g_dscore[(size_t)Bz * Dd * Dd];  // 32 MB
__device__ float g_lscore[(size_t)Bz * Ll * Ll];  // 128 MB
__device__ float g_ss[(size_t)Bz * Ll];
__device__ float g_cs[(size_t)Bz * Ll];

// ---------------------------------------------------------------------------
// Generic SGEMM: C[b] = op(A[b]) * op(B[b]) (+ epilogue)
//   TA=0: A is M x K (lda = row stride);  TA=1: A is K x M
//   TB=0: B is K x N;                     TB=1: B is N x K
//   EPI=0: C = acc
//   EPI=1: C = acc + aux[m]              (per-row bias)
//   EPI=2: C = (acc + aux[b,m,n]) * 0.5  (residual average)
// Block tile 128x128, K-step 8, 256 threads, 8x8 per thread.
// Requires M,N % 128 == 0, K % 8 == 0, all leading dims % 4 == 0.
// ---------------------------------------------------------------------------
template <int TA, int TB, int EPI>
__global__ void __launch_bounds__(256, 2) gemm_kernel(
    int M, int N, int K,
    const float* __restrict__ A, int lda, long strideA,
    const float* __restrict__ B, int ldb, long strideB,
    float* __restrict__ C, int ldc, long strideC,
    const float* __restrict__ aux, long strideAux)
{
    __shared__ float As[8][128];
    __shared__ float Bs[8][132];   // +4 pad; row stride 132 floats = 16B aligned

    const int tid = threadIdx.x;
    const int tx = tid & 15;       // n direction
    const int ty = tid >> 4;       // m direction
    const int m0 = blockIdx.y * 128;
    const int n0 = blockIdx.x * 128;
    const int bz = blockIdx.z;

    A += (long)bz * strideA;
    B += (long)bz * strideB;
    C += (long)bz * strideC;

    float acc[8][8];
#pragma unroll
    for (int i = 0; i < 8; i++)
#pragma unroll
        for (int j = 0; j < 8; j++) acc[i][j] = 0.f;

    for (int k0 = 0; k0 < K; k0 += 8) {
        // ---- load A tile into As[k][m] ----
        if (!TA) {
            int r = tid >> 1;             // 0..127 (m)
            int c = (tid & 1) * 4;        // 0 or 4 (k)
            float4 v = *(const float4*)&A[(long)(m0 + r) * lda + k0 + c];
            As[c + 0][r] = v.x; As[c + 1][r] = v.y;
            As[c + 2][r] = v.z; As[c + 3][r] = v.w;
        } else {
            int r = tid >> 5;             // 0..7  (k)
            int c = (tid & 31) * 4;       // 0..124 (m)
            float4 v = *(const float4*)&A[(long)(k0 + r) * lda + m0 + c];
            *(float4*)&As[r][c] = v;
        }
        // ---- load B tile into Bs[k][n] ----
        if (!TB) {
            int r = tid >> 5;             // k
            int c = (tid & 31) * 4;       // n
            float4 v = *(const float4*)&B[(long)(k0 + r) * ldb + n0 + c];
            *(float4*)&Bs[r][c] = v;
        } else {
            int r = tid >> 1;             // n
            int c = (tid & 1) * 4;        // k
            float4 v = *(const float4*)&B[(long)(n0 + r) * ldb + k0 + c];
            Bs[c + 0][r] = v.x; Bs[c + 1][r] = v.y;
            Bs[c + 2][r] = v.z; Bs[c + 3][r] = v.w;
        }
        __syncthreads();

#pragma unroll
        for (int kk = 0; kk < 8; kk++) {
            float a[8], b[8];
            *(float4*)&a[0] = *(const float4*)&As[kk][ty * 8];
            *(float4*)&a[4] = *(const float4*)&As[kk][ty * 8 + 4];
            *(float4*)&b[0] = *(const float4*)&Bs[kk][tx * 8];
            *(float4*)&b[4] = *(const float4*)&Bs[kk][tx * 8 + 4];
#pragma unroll
            for (int i = 0; i < 8; i++)
#pragma unroll
                for (int j = 0; j < 8; j++)
                    acc[i][j] = fmaf(a[i], b[j], acc[i][j]);
        }
        __syncthreads();
    }

    // ---- epilogue ----
#pragma unroll
    for (int i = 0; i < 8; i++) {
        int m = m0 + ty * 8 + i;
        float bias = 0.f;
        if (EPI == 1) bias = aux[m];
#pragma unroll
        for (int j = 0; j < 8; j += 4) {
            int n = n0 + tx * 8 + j;
            float4 r;
            r.x = acc[i][j + 0]; r.y = acc[i][j + 1];
            r.z = acc[i][j + 2]; r.w = acc[i][j + 3];
            if (EPI == 1) { r.x += bias; r.y += bias; r.z += bias; r.w += bias; }
            if (EPI == 2) {
                float4 xres = *(const float4*)&aux[(long)bz * strideAux + (long)m * ldc + n];
                r.x = (r.x + xres.x) * 0.5f; r.y = (r.y + xres.y) * 0.5f;
                r.z = (r.z + xres.z) * 0.5f; r.w = (r.w + xres.w) * 0.5f;
            }
            *(float4*)&C[(long)m * ldc + n] = r;
        }
    }
}

// ---------------------------------------------------------------------------
// Reductions & pointwise
// ---------------------------------------------------------------------------
__device__ __forceinline__ float blockReduceSum(float v) {
    __shared__ float sm[32];
    __syncthreads();
    int lane = threadIdx.x & 31, w = threadIdx.x >> 5;
#pragma unroll
    for (int o = 16; o; o >>= 1) v += __shfl_down_sync(0xffffffffu, v, o);
    if (!lane) sm[w] = v;
    __syncthreads();
    int nw = blockDim.x >> 5;
    v = (threadIdx.x < nw) ? sm[threadIdx.x] : 0.f;
    if (w == 0) {
#pragma unroll
        for (int o = 16; o; o >>= 1) v += __shfl_down_sync(0xffffffffu, v, o);
        if (!lane) sm[0] = v;
    }
    __syncthreads();
    return sm[0];
}

__device__ __forceinline__ float blockReduceMax(float v) {
    __shared__ float sm[32];
    __syncthreads();
    int lane = threadIdx.x & 31, w = threadIdx.x >> 5;
#pragma unroll
    for (int o = 16; o; o >>= 1) v = fmaxf(v, __shfl_down_sync(0xffffffffu, v, o));
    if (!lane) sm[w] = v;
    __syncthreads();
    int nw = blockDim.x >> 5;
    v = (threadIdx.x < nw) ? sm[threadIdx.x] : -1e30f;
    if (w == 0) {
#pragma unroll
        for (int o = 16; o; o >>= 1) v = fmaxf(v, __shfl_down_sync(0xffffffffu, v, o));
        if (!lane) sm[0] = v;
    }
    __syncthreads();
    return sm[0];
}

// out[row] = sum over contiguous Lc of X[row,:]^2   (one block per row)
__global__ void rowsq_kernel(const float* __restrict__ X, float* __restrict__ out, int Lc) {
    long row = blockIdx.x;
    const float* p = X + row * (long)Lc;
    float s = 0.f;
    for (int i = threadIdx.x * 4; i < Lc; i += blockDim.x * 4) {
        float4 v = *(const float4*)&p[i];
        s += v.x * v.x + v.y * v.y + v.z * v.z + v.w * v.w;
    }
    s = blockReduceSum(s);
    if (threadIdx.x == 0) out[row] = s;
}

// out[b*Ln + l] = sum_d X[b,d,l]^2   (thread per (b,l), strided-but-coalesced)
__global__ void colsq_kernel(const float* __restrict__ X, float* __restrict__ out, int Dn, int Ln) {
    int l = blockIdx.x * blockDim.x + threadIdx.x;
    int b = blockIdx.z;
    const float* p = X + (long)b * Dn * Ln + l;
    float s = 0.f;
    for (int d = 0; d < Dn; d++) {
        float v = p[(long)d * Ln];
        s = fmaf(v, v, s);
    }
    out[(long)b * Ln + l] = s;
}

// In-place: S = relu(0.5 - 0.5*cos(pi*((S^2/(ss[m]*cs[n]))^e - eye)))
__global__ void cauchy_kernel(float* __restrict__ S,
                              const float* __restrict__ ss,
                              const float* __restrict__ cs, int M) {
    long idx = (long)blockIdx.x * blockDim.x + threadIdx.x;
    long total = (long)Bz * M * M;
    if (idx >= total) return;
    int c = (int)(idx % M);
    int r = (int)((idx / M) % M);
    int b = (int)(idx / ((long)M * M));
    float mm = S[idx];
    float v = (mm * mm) / (ss[(long)b * M + r] * cs[(long)b * M + c]);
    float p = powf(v, CAUCHY_E);
    if (r == c) p -= 1.0f;
    float o = 0.5f - 0.5f * cospif(p);
    S[idx] = fmaxf(o, 0.0f);
}

// softmax over axis 1 of (B, M, M): per (b, n) column. Thread per column.
__global__ void softmax_col_kernel(float* __restrict__ S, int M) {
    int n = blockIdx.x * blockDim.x + threadIdx.x;
    int b = blockIdx.z;
    float* base = S + (long)b * M * M + n;
    float mx = -1e30f;
    for (int m = 0; m < M; m++) mx = fmaxf(mx, base[(long)m * M]);
    float s = 0.f;
    for (int m = 0; m < M; m++) {
        float e = expf(base[(long)m * M] - mx);
        base[(long)m * M] = e;
        s += e;
    }
    float inv = 1.0f / s;
    for (int m = 0; m < M; m++) base[(long)m * M] *= inv;
}

// softmax over last axis, one block per row of length n
__global__ void softmax_row_kernel(float* __restrict__ S, int n) {
    float* p = S + (long)blockIdx.x * n;
    float mx = -1e30f;
    for (int i = threadIdx.x; i < n; i += blockDim.x) mx = fmaxf(mx, p[i]);
    mx = blockReduceMax(mx);
    float s = 0.f;
    for (int i = threadIdx.x; i < n; i += blockDim.x) {
        float e = expf(p[i] - mx);
        p[i] = e;
        s += e;
    }
    s = blockReduceSum(s);
    float inv = 1.0f / s;
    for (int i = threadIdx.x; i < n; i += blockDim.x) p[i] *= inv;
}

// ---------------------------------------------------------------------------
// Orchestration
// ---------------------------------------------------------------------------
extern "C" void kernel_launch(void* const* d_in, const int* in_sizes, int n_in,
                              void* d_out, int out_size) {
    (void)in_sizes; (void)n_in; (void)out_size;
    const float* x = (const float*)d_in[0];
    const float* W[4] = {(const float*)d_in[1], (const float*)d_in[3],
                         (const float*)d_in[5], (const float*)d_in[7]};
    const float* bv[4] = {(const float*)d_in[2], (const float*)d_in[4],
                          (const float*)d_in[6], (const float*)d_in[8]};
    float* out = (float*)d_out;

    float *t1, *t2, *sx, *cx, *dsc, *lsc, *ss, *cs;
    cudaGetSymbolAddress((void**)&t1,  g_t1);
    cudaGetSymbolAddress((void**)&t2,  g_t2);
    cudaGetSymbolAddress((void**)&sx,  g_sx);
    cudaGetSymbolAddress((void**)&cx,  g_cx);
    cudaGetSymbolAddress((void**)&dsc, g_dscore);
    cudaGetSymbolAddress((void**)&lsc, g_lscore);
    cudaGetSymbolAddress((void**)&ss,  g_ss);
    cudaGetSymbolAddress((void**)&cs,  g_cs);

    const long sXDL = (long)Dd * Ll;
    const dim3 blk(256);
    const dim3 gMLP(Ll / 128, Dd / 128, Bz);

    // 3-layer pointwise MLP: dst = L3(L2(L1(x)))
    auto mlp = [&](const float* Wi, const float* bi, float* dst) {
        gemm_kernel<0, 0, 1><<<gMLP, blk>>>(Dd, Ll, Dd,
            Wi, Dd, 0, x, Ll, sXDL, t1, Ll, sXDL, bi, 0);
        gemm_kernel<0, 0, 1><<<gMLP, blk>>>(Dd, Ll, Dd,
            Wi + (long)Dd * Dd, Dd, 0, t1, Ll, sXDL, t2, Ll, sXDL, bi + Dd, 0);
        gemm_kernel<0, 0, 1><<<gMLP, blk>>>(Dd, Ll, Dd,
            Wi + 2L * Dd * Dd, Dd, 0, t2, Ll, sXDL, dst, Ll, sXDL, bi + 2 * Dd, 0);
    };

    // ---------------- dscore branch ----------------
    mlp(W[0], bv[0], sx);   // dsx
    mlp(W[1], bv[1], cx);   // dcx
    rowsq_kernel<<<Bz * Dd, 256>>>(sx, ss, Ll);
    rowsq_kernel<<<Bz * Dd, 256>>>(cx, cs, Ll);
    // dnum = dsx @ dcx^T : NT, (D x D), K = L
    gemm_kernel<0, 1, 0><<<dim3(Dd / 128, Dd / 128, Bz), blk>>>(Dd, Dd, Ll,
        sx, Ll, sXDL, cx, Ll, sXDL, dsc, Dd, (long)Dd * Dd, nullptr, 0);
    {
        long total = (long)Bz * Dd * Dd;
        cauchy_kernel<<<(unsigned)((total + 255) / 256), 256>>>(dsc, ss, cs, Dd);
    }
    softmax_col_kernel<<<dim3(Dd / 256, 1, Bz), 256>>>(dsc, Dd);

    // ---------------- lscore branch ----------------
    mlp(W[2], bv[2], sx);   // lsx
    mlp(W[3], bv[3], cx);   // lcx
    colsq_kernel<<<dim3(Ll / 256, 1, Bz), 256>>>(sx, ss, Dd, Ll);
    colsq_kernel<<<dim3(Ll / 256, 1, Bz), 256>>>(cx, cs, Dd, Ll);
    // lnum = lsx^T @ lcx : TN, (L x L), K = D
    gemm_kernel<1, 0, 0><<<dim3(Ll / 128, Ll / 128, Bz), blk>>>(Ll, Ll, Dd,
        sx, Ll, sXDL, cx, Ll, sXDL, lsc, Ll, (long)Ll * Ll, nullptr, 0);
    {
        long total = (long)Bz * Ll * Ll;
        cauchy_kernel<<<(unsigned)((total + 255) / 256), 256>>>(lsc, ss, cs, Ll);
    }
    softmax_row_kernel<<<Bz * Ll, 256>>>(lsc, Ll);

    // ---------------- combine ----------------
    // T = dscore @ x  (D x L, K = D)
    gemm_kernel<0, 0, 0><<<gMLP, blk>>>(Dd, Ll, Dd,
        dsc, Dd, (long)Dd * Dd, x, Ll, sXDL, t1, Ll, sXDL, nullptr, 0);
    // out = (T @ lscore + x) / 2  (D x L, K = L)
    gemm_kernel<0, 0, 2><<<gMLP, blk>>>(Dd, Ll, Ll,
        t1, Ll, sXDL, lsc, Ll, (long)Ll * Ll, out, Ll, sXDL, x, sXDL);
}

// round 7
// speedup vs baseline: 1.5767x; 1.5745x over previous
#include <cuda_runtime.h>
#include <cuda_fp16.h>
#include <cstdint>
#include <math.h>

#define Bz 8
#define Dd 1024
#define Ll 2048
#define CAUCHY_E 1.0100501670841680575f
#define PI_F 3.14159265358979323846f

typedef __half h16;

// ============================ device scratch ===============================
#define NLD ((size_t)Bz * Ll * Dd)
__device__ __align__(16) h16 g_wh[(size_t)12 * Dd * Dd], g_wl[(size_t)12 * Dd * Dd];
__device__ __align__(16) h16 g_xth[NLD], g_xtl[NLD];
__device__ __align__(16) h16 g_p1h[NLD], g_p1l[NLD];
__device__ __align__(16) h16 g_p2h[NLD], g_p2l[NLD];
__device__ __align__(16) h16 g_sxh[NLD], g_sxl[NLD];
__device__ __align__(16) h16 g_cxh[NLD], g_cxl[NLD];
__device__ __align__(16) h16 g_dsph[(size_t)Bz * Dd * Dd], g_dspl[(size_t)Bz * Dd * Dd];
__device__ __align__(16) h16 g_lsth[(size_t)Bz * Ll * Ll], g_lstl[(size_t)Bz * Ll * Ll];
__device__ __align__(16) float g_dnum[(size_t)Bz * Dd * Dd];
__device__ __align__(16) float g_lnum[(size_t)Bz * Ll * Ll];
__device__ float g_ss[(size_t)Bz * Ll], g_cs[(size_t)Bz * Ll];

// ============================= mma helpers =================================
__device__ __forceinline__ void mma16816(float* c, const uint32_t* a, const uint32_t* b) {
    asm volatile(
        "mma.sync.aligned.m16n8k16.row.col.f32.f16.f16.f32 "
        "{%0,%1,%2,%3}, {%4,%5,%6,%7}, {%8,%9}, {%0,%1,%2,%3};"
        : "+f"(c[0]), "+f"(c[1]), "+f"(c[2]), "+f"(c[3])
        : "r"(a[0]), "r"(a[1]), "r"(a[2]), "r"(a[3]), "r"(b[0]), "r"(b[1]));
}
__device__ __forceinline__ void ldsm_x4(uint32_t* r, uint32_t addr) {
    asm volatile("ldmatrix.sync.aligned.m8n8.x4.shared.b16 {%0,%1,%2,%3}, [%4];"
                 : "=r"(r[0]), "=r"(r[1]), "=r"(r[2]), "=r"(r[3]) : "r"(addr));
}
__device__ __forceinline__ void ldsm_x2(uint32_t* r, uint32_t addr) {
    asm volatile("ldmatrix.sync.aligned.m8n8.x2.shared.b16 {%0,%1}, [%2];"
                 : "=r"(r[0]), "=r"(r[1]) : "r"(addr));
}
__device__ __forceinline__ uint32_t smem_u32(const void* p) {
    uint32_t a;
    asm("{ .reg .u64 t; cvta.to.shared.u64 t, %1; cvt.u32.u64 %0, t; }" : "=r"(a) : "l"(p));
    return a;
}
__device__ __forceinline__ void cp_async16(uint32_t d, const void* g) {
    asm volatile("cp.async.ca.shared.global [%0], [%1], 16;" :: "r"(d), "l"(g));
}

// ===========================================================================
// split-fp16 GEMM via mma.sync: C[b] = A[b] * B[b]^T
// A: MxK (K-major), B: NxK (K-major), (hi,lo) pairs; product = hh + hl + lh.
// CTA 128x128, 256 thr (8 warps: 2M x 4N, warp tile 64x32), K-chunk 32,
// cp.async double buffer. Row pad: 32 halves -> 80 bytes (conflict-free).
// EPI 0: fp32 out   EPI 1: h16 pair + bias[n]   EPI 2: h16 pair
// EPI 3: fp32 out = (acc + aux)/2
// ===========================================================================
#define ROWB 80
#define BUFB 10240            // 128 rows * 80B
#define STAGEB 40960          // 4 buffers (Ah, Al, Bh, Bl)
#define SMEMB (2 * STAGEB)

template <int EPI>
__global__ void __launch_bounds__(256, 1) gemm_mma(
    int M, int N, int K,
    const h16* __restrict__ Ah, const h16* __restrict__ Al, long sA,
    const h16* __restrict__ Bh, const h16* __restrict__ Bl, long sB,
    float* __restrict__ C, h16* __restrict__ Ch, h16* __restrict__ Cl, long sC,
    const float* __restrict__ aux, long sAux)
{
    extern __shared__ __align__(16) char smem[];
    const uint32_t su = smem_u32(smem);
    const int tid = threadIdx.x;
    const int wid = tid >> 5, lane = tid & 31;
    const int gid = lane >> 2, tig = lane & 3;
    const int warpM = wid >> 2, warpN = wid & 3;     // 2 x 4
    const int m0 = blockIdx.y * 128, n0 = blockIdx.x * 128, bz = blockIdx.z;

    const h16* pAh = Ah + (long)bz * sA;
    const h16* pAl = Al + (long)bz * sA;
    const h16* pBh = Bh + (long)bz * sB;
    const h16* pBl = Bl + (long)bz * sB;

    auto issue = [&](int stage, int k0) {
        const uint32_t sb = su + stage * STAGEB;
        #pragma unroll
        for (int t = 0; t < 8; ++t) {
            int idx = tid + t * 256;
            int buf = idx >> 9, r = (idx >> 2) & 127, ch = idx & 3;
            const h16* g;
            if (buf == 0)      g = pAh + (long)(m0 + r) * K + k0 + ch * 8;
            else if (buf == 1) g = pAl + (long)(m0 + r) * K + k0 + ch * 8;
            else if (buf == 2) g = pBh + (long)(n0 + r) * K + k0 + ch * 8;
            else               g = pBl + (long)(n0 + r) * K + k0 + ch * 8;
            cp_async16(sb + buf * BUFB + r * ROWB + ch * 16, g);
        }
    };

    float acc[4][4][4];
    #pragma unroll
    for (int i = 0; i < 4; i++)
        #pragma unroll
        for (int j = 0; j < 4; j++)
            #pragma unroll
            for (int q = 0; q < 4; q++) acc[i][j][q] = 0.f;

    const int nch = K >> 5;
    issue(0, 0);
    asm volatile("cp.async.commit_group;" ::: "memory");

    // per-lane fragment address components
    const int arow = (lane < 16) ? lane : (lane - 16);
    const int acolx = (lane < 16) ? 0 : 8;
    const int bl8 = lane & 7;
    const int bsel = (lane >> 3) & 1;

    for (int c = 0; c < nch; ++c) {
        if (c + 1 < nch) {
            issue((c + 1) & 1, (c + 1) << 5);
            asm volatile("cp.async.commit_group;" ::: "memory");
            asm volatile("cp.async.wait_group 1;" ::: "memory");
        } else {
            asm volatile("cp.async.wait_group 0;" ::: "memory");
        }
        __syncthreads();

        const uint32_t sb = su + (c & 1) * STAGEB;
        #pragma unroll
        for (int kk = 0; kk < 32; kk += 16) {
            uint32_t ah[4][4], al[4][4], bh[4][2], bl[4][2];
            #pragma unroll
            for (int mt = 0; mt < 4; ++mt) {
                uint32_t ad = sb + (warpM * 64 + mt * 16 + arow) * ROWB + (kk + acolx) * 2;
                ldsm_x4(ah[mt], ad);
                ldsm_x4(al[mt], ad + BUFB);
            }
            #pragma unroll
            for (int nt = 0; nt < 4; ++nt) {
                uint32_t bd = sb + 2 * BUFB +
                              (warpN * 32 + nt * 8 + bl8) * ROWB + (kk + bsel * 8) * 2;
                ldsm_x2(bh[nt], bd);
                ldsm_x2(bl[nt], bd + BUFB);
            }
            #pragma unroll
            for (int mt = 0; mt < 4; ++mt)
                #pragma unroll
                for (int nt = 0; nt < 4; ++nt) {
                    mma16816(acc[mt][nt], ah[mt], bh[nt]);   // hh
                    mma16816(acc[mt][nt], ah[mt], bl[nt]);   // hl
                    mma16816(acc[mt][nt], al[mt], bh[nt]);   // lh
                }
        }
        __syncthreads();
    }

    // ------------------------------ epilogue ------------------------------
    #pragma unroll
    for (int mt = 0; mt < 4; ++mt) {
        const int r0 = m0 + warpM * 64 + mt * 16 + gid;
        #pragma unroll
        for (int nt = 0; nt < 4; ++nt) {
            const int cc = n0 + warpN * 32 + nt * 8 + tig * 2;
            float* a = acc[mt][nt];
            if (EPI == 0) {
                float* cp = C + (long)bz * sC;
                *(float2*)(cp + (long)r0 * N + cc)       = make_float2(a[0], a[1]);
                *(float2*)(cp + (long)(r0 + 8) * N + cc) = make_float2(a[2], a[3]);
            } else if (EPI == 1 || EPI == 2) {
                float v0 = a[0], v1 = a[1], v2 = a[2], v3 = a[3];
                if (EPI == 1) {
                    float b0 = aux[cc], b1 = aux[cc + 1];
                    v0 += b0; v1 += b1; v2 += b0; v3 += b1;
                }
                h16* hp = Ch + (long)bz * sC;
                h16* lp = Cl + (long)bz * sC;
                h16 h0 = __float2half_rn(v0), h1 = __float2half_rn(v1);
                h16 h2 = __float2half_rn(v2), h3 = __float2half_rn(v3);
                *(__half2*)(hp + (long)r0 * N + cc) = __halves2half2(h0, h1);
                *(__half2*)(hp + (long)(r0 + 8) * N + cc) = __halves2half2(h2, h3);
                *(__half2*)(lp + (long)r0 * N + cc) = __halves2half2(
                    __float2half_rn(v0 - __half2float(h0)), __float2half_rn(v1 - __half2float(h1)));
                *(__half2*)(lp + (long)(r0 + 8) * N + cc) = __halves2half2(
                    __float2half_rn(v2 - __half2float(h2)), __float2half_rn(v3 - __half2float(h3)));
            } else {
                const float* xp = aux + (long)bz * sAux;
                float* cp = C + (long)bz * sC;
                float2 x0 = *(const float2*)(xp + (long)r0 * N + cc);
                float2 x1 = *(const float2*)(xp + (long)(r0 + 8) * N + cc);
                *(float2*)(cp + (long)r0 * N + cc) =
                    make_float2((a[0] + x0.x) * 0.5f, (a[1] + x0.y) * 0.5f);
                *(float2*)(cp + (long)(r0 + 8) * N + cc) =
                    make_float2((a[2] + x1.x) * 0.5f, (a[3] + x1.y) * 0.5f);
            }
        }
    }
}

// ========================= conversions / pointwise =========================
__global__ void split_kernel(const float4* __restrict__ in,
                             __half2* __restrict__ h2, __half2* __restrict__ l2, long n4) {
    long i = (long)blockIdx.x * blockDim.x + threadIdx.x;
    if (i >= n4) return;
    float4 v = in[i];
    h16 ha = __float2half_rn(v.x), hb = __float2half_rn(v.y);
    h16 hc = __float2half_rn(v.z), hd = __float2half_rn(v.w);
    h2[2 * i]     = __halves2half2(ha, hb);
    h2[2 * i + 1] = __halves2half2(hc, hd);
    l2[2 * i]     = __halves2half2(__float2half_rn(v.x - __half2float(ha)),
                                   __float2half_rn(v.y - __half2float(hb)));
    l2[2 * i + 1] = __halves2half2(__float2half_rn(v.z - __half2float(hc)),
                                   __float2half_rn(v.w - __half2float(hd)));
}

// fp32 [z][R][C] -> (hi,lo) h16 [z][C][R]
__global__ void split_transpose(const float* __restrict__ in,
                                h16* __restrict__ oh, h16* __restrict__ ol, int R, int C) {
    __shared__ float t[32][33];
    const long ob = (long)blockIdx.z * R * C;
    int r0 = blockIdx.y * 32, c0 = blockIdx.x * 32;
    int tx = threadIdx.x, ty = threadIdx.y;
    #pragma unroll
    for (int i = 0; i < 4; i++)
        t[ty + i * 8][tx] = in[ob + (long)(r0 + ty + i * 8) * C + c0 + tx];
    __syncthreads();
    #pragma unroll
    for (int i = 0; i < 4; i++) {
        int oc = c0 + ty + i * 8;
        float v = t[tx][ty + i * 8];
        h16 h = __float2half_rn(v);
        oh[ob + (long)oc * R + r0 + tx] = h;
        ol[ob + (long)oc * R + r0 + tx] = __float2half_rn(v - __half2float(h));
    }
}

// 16-bit [z][R][C] -> [z][C][R] (bit-exact move)
__global__ void transpose_u16(const unsigned short* __restrict__ in,
                              unsigned short* __restrict__ out, int R, int C) {
    __shared__ unsigned short t[32][34];
    const long ob = (long)blockIdx.z * R * C;
    int r0 = blockIdx.y * 32, c0 = blockIdx.x * 32;
    int tx = threadIdx.x, ty = threadIdx.y;
    #pragma unroll
    for (int i = 0; i < 4; i++)
        t[ty + i * 8][tx] = in[ob + (long)(r0 + ty + i * 8) * C + c0 + tx];
    __syncthreads();
    #pragma unroll
    for (int i = 0; i < 4; i++)
        out[ob + (long)(c0 + ty + i * 8) * R + r0 + tx] = t[tx][ty + i * 8];
}

__device__ __forceinline__ float blockReduceSum(float v) {
    __shared__ float sm[32];
    __syncthreads();
    int lane = threadIdx.x & 31, w = threadIdx.x >> 5;
    #pragma unroll
    for (int o = 16; o; o >>= 1) v += __shfl_down_sync(0xffffffffu, v, o);
    if (!lane) sm[w] = v;
    __syncthreads();
    int nw = blockDim.x >> 5;
    v = (threadIdx.x < nw) ? sm[threadIdx.x] : 0.f;
    if (w == 0) {
        #pragma unroll
        for (int o = 16; o; o >>= 1) v += __shfl_down_sync(0xffffffffu, v, o);
        if (!lane) sm[0] = v;
    }
    __syncthreads();
    return sm[0];
}
__device__ __forceinline__ float blockReduceMax(float v) {
    __shared__ float sm[32];
    __syncthreads();
    int lane = threadIdx.x & 31, w = threadIdx.x >> 5;
    #pragma unroll
    for (int o = 16; o; o >>= 1) v = fmaxf(v, __shfl_down_sync(0xffffffffu, v, o));
    if (!lane) sm[w] = v;
    __syncthreads();
    int nw = blockDim.x >> 5;
    v = (threadIdx.x < nw) ? sm[threadIdx.x] : -1e30f;
    if (w == 0) {
        #pragma unroll
        for (int o = 16; o; o >>= 1) v = fmaxf(v, __shfl_down_sync(0xffffffffu, v, o));
        if (!lane) sm[0] = v;
    }
    __syncthreads();
    return sm[0];
}

// per-row sum of (hi+lo)^2, contiguous length C; one block per row
__global__ void sumsq_row_pair(const h16* __restrict__ h, const h16* __restrict__ l,
                               float* __restrict__ out, int C) {
    long row = blockIdx.x;
    const h16* hp = h + row * (long)C;
    const h16* lp = l + row * (long)C;
    float s = 0.f;
    for (int i = threadIdx.x; i < C; i += blockDim.x) {
        float v = __half2float(hp[i]) + __half2float(lp[i]);
        s = fmaf(v, v, s);
    }
    s = blockReduceSum(s);
    if (threadIdx.x == 0) out[row] = s;
}

__global__ void cauchy_kernel(float* __restrict__ S, const float* __restrict__ ss,
                              const float* __restrict__ cs, int M) {
    long idx = (long)blockIdx.x * blockDim.x + threadIdx.x;
    long total = (long)Bz * M * M;
    if (idx >= total) return;
    int c = (int)(idx % M);
    int r = (int)((idx / M) % M);
    int b = (int)(idx / ((long)M * M));
    float mm = S[idx];
    float v = (mm * mm) / (ss[(long)b * M + r] * cs[(long)b * M + c]);
    float p = powf(v, CAUCHY_E);
    if (r == c) p -= 1.0f;
    float o = 0.5f - 0.5f * cospif(p);
    S[idx] = fmaxf(o, 0.0f);
}

// softmax over rows (axis 1) of (B, M, M): thread per column
__global__ void softmax_col_kernel(float* __restrict__ S, int M) {
    int n = blockIdx.x * blockDim.x + threadIdx.x;
    int b = blockIdx.z;
    float* base = S + (long)b * M * M + n;
    float mx = -1e30f;
    for (int m = 0; m < M; m++) mx = fmaxf(mx, base[(long)m * M]);
    float s = 0.f;
    for (int m = 0; m < M; m++) {
        float e = __expf(base[(long)m * M] - mx);
        base[(long)m * M] = e;
        s += e;
    }
    float inv = 1.0f / s;
    for (int m = 0; m < M; m++) base[(long)m * M] *= inv;
}

// softmax over last axis; one block per row
__global__ void softmax_row_kernel(float* __restrict__ S, int n) {
    float* p = S + (long)blockIdx.x * n;
    float mx = -1e30f;
    for (int i = threadIdx.x; i < n; i += blockDim.x) mx = fmaxf(mx, p[i]);
    mx = blockReduceMax(mx);
    float s = 0.f;
    for (int i = threadIdx.x; i < n; i += blockDim.x) {
        float e = __expf(p[i] - mx);
        p[i] = e;
        s += e;
    }
    s = blockReduceSum(s);
    float inv = 1.0f / s;
    for (int i = threadIdx.x; i < n; i += blockDim.x) p[i] *= inv;
}

// ============================= orchestration ===============================
extern "C" void kernel_launch(void* const* d_in, const int* in_sizes, int n_in,
                              void* d_out, int out_size) {
    (void)in_sizes; (void)n_in; (void)out_size;
    const float* x = (const float*)d_in[0];
    const float* W[4] = {(const float*)d_in[1], (const float*)d_in[3],
                         (const float*)d_in[5], (const float*)d_in[7]};
    const float* bb[4] = {(const float*)d_in[2], (const float*)d_in[4],
                          (const float*)d_in[6], (const float*)d_in[8]};
    float* out = (float*)d_out;

    h16 *wh, *wl, *xth, *xtl, *p1h, *p1l, *p2h, *p2l, *sxh, *sxl, *cxh, *cxl;
    h16 *dsph, *dspl, *lsth, *lstl;
    float *dnum, *lnum, *ss, *cs;
    cudaGetSymbolAddress((void**)&wh, g_wh);   cudaGetSymbolAddress((void**)&wl, g_wl);
    cudaGetSymbolAddress((void**)&xth, g_xth); cudaGetSymbolAddress((void**)&xtl, g_xtl);
    cudaGetSymbolAddress((void**)&p1h, g_p1h); cudaGetSymbolAddress((void**)&p1l, g_p1l);
    cudaGetSymbolAddress((void**)&p2h, g_p2h); cudaGetSymbolAddress((void**)&p2l, g_p2l);
    cudaGetSymbolAddress((void**)&sxh, g_sxh); cudaGetSymbolAddress((void**)&sxl, g_sxl);
    cudaGetSymbolAddress((void**)&cxh, g_cxh); cudaGetSymbolAddress((void**)&cxl, g_cxl);
    cudaGetSymbolAddress((void**)&dsph, g_dsph); cudaGetSymbolAddress((void**)&dspl, g_dspl);
    cudaGetSymbolAddress((void**)&lsth, g_lsth); cudaGetSymbolAddress((void**)&lstl, g_lstl);
    cudaGetSymbolAddress((void**)&dnum, g_dnum); cudaGetSymbolAddress((void**)&lnum, g_lnum);
    cudaGetSymbolAddress((void**)&ss, g_ss);   cudaGetSymbolAddress((void**)&cs, g_cs);

    cudaFuncSetAttribute(gemm_mma<0>, cudaFuncAttributeMaxDynamicSharedMemorySize, SMEMB);
    cudaFuncSetAttribute(gemm_mma<1>, cudaFuncAttributeMaxDynamicSharedMemorySize, SMEMB);
    cudaFuncSetAttribute(gemm_mma<2>, cudaFuncAttributeMaxDynamicSharedMemorySize, SMEMB);
    cudaFuncSetAttribute(gemm_mma<3>, cudaFuncAttributeMaxDynamicSharedMemorySize, SMEMB);

    const long LD = (long)Ll * Dd;
    const long DDm = (long)Dd * Dd;
    const long LLm = (long)Ll * Ll;
    const dim3 tb(32, 8);

    // ---- input conversions ----
    for (int i = 0; i < 4; i++) {
        long n4 = 3L * Dd * Dd / 4;
        split_kernel<<<(unsigned)((n4 + 255) / 256), 256>>>(
            (const float4*)W[i],
            (__half2*)(wh + (size_t)i * 3 * Dd * Dd),
            (__half2*)(wl + (size_t)i * 3 * Dd * Dd), n4);
    }
    split_transpose<<<dim3(Ll / 32, Dd / 32, Bz), tb>>>(x, xth, xtl, Dd, Ll);  // x -> LD pair

    // ---- 3-layer pointwise MLP in LD layout ----
    const dim3 gM(Dd / 128, Ll / 128, Bz);
    auto mlp = [&](int wi, const float* bias, h16* oh, h16* ol) {
        const h16* wph = wh + (size_t)wi * 3 * Dd * Dd;
        const h16* wpl = wl + (size_t)wi * 3 * Dd * Dd;
        gemm_mma<1><<<gM, 256, SMEMB>>>(Ll, Dd, Dd, xth, xtl, LD, wph, wpl, 0,
                                        nullptr, p1h, p1l, LD, bias, 0);
        gemm_mma<1><<<gM, 256, SMEMB>>>(Ll, Dd, Dd, p1h, p1l, LD, wph + DDm, wpl + DDm, 0,
                                        nullptr, p2h, p2l, LD, bias + Dd, 0);
        gemm_mma<1><<<gM, 256, SMEMB>>>(Ll, Dd, Dd, p2h, p2l, LD, wph + 2 * DDm, wpl + 2 * DDm, 0,
                                        nullptr, oh, ol, LD, bias + 2 * Dd, 0);
    };

    // ---------------- dscore branch ----------------
    mlp(0, bb[0], sxh, sxl);   // dsx (LD)
    mlp(1, bb[1], cxh, cxl);   // dcx (LD)
    transpose_u16<<<dim3(Dd / 32, Ll / 32, Bz), tb>>>((const unsigned short*)sxh, (unsigned short*)p1h, Ll, Dd);
    transpose_u16<<<dim3(Dd / 32, Ll / 32, Bz), tb>>>((const unsigned short*)sxl, (unsigned short*)p1l, Ll, Dd);
    transpose_u16<<<dim3(Dd / 32, Ll / 32, Bz), tb>>>((const unsigned short*)cxh, (unsigned short*)p2h, Ll, Dd);
    transpose_u16<<<dim3(Dd / 32, Ll / 32, Bz), tb>>>((const unsigned short*)cxl, (unsigned short*)p2l, Ll, Dd);
    sumsq_row_pair<<<Bz * Dd, 256>>>(p1h, p1l, ss, Ll);
    sumsq_row_pair<<<Bz * Dd, 256>>>(p2h, p2l, cs, Ll);
    gemm_mma<0><<<dim3(Dd / 128, Dd / 128, Bz), 256, SMEMB>>>(Dd, Dd, Ll,
        p1h, p1l, LD, p2h, p2l, LD, dnum, nullptr, nullptr, DDm, nullptr, 0);
    cauchy_kernel<<<(unsigned)((Bz * DDm + 255) / 256), 256>>>(dnum, ss, cs, Dd);
    softmax_col_kernel<<<dim3(Dd / 256, 1, Bz), 256>>>(dnum, Dd);
    split_kernel<<<(unsigned)((Bz * DDm / 4 + 255) / 256), 256>>>(
        (const float4*)dnum, (__half2*)dsph, (__half2*)dspl, Bz * DDm / 4);

    // ---------------- lscore branch ----------------
    mlp(2, bb[2], sxh, sxl);   // lsx (LD)
    mlp(3, bb[3], cxh, cxl);   // lcx (LD)
    sumsq_row_pair<<<Bz * Ll, 256>>>(sxh, sxl, ss, Dd);
    sumsq_row_pair<<<Bz * Ll, 256>>>(cxh, cxl, cs, Dd);
    gemm_mma<0><<<dim3(Ll / 128, Ll / 128, Bz), 256, SMEMB>>>(Ll, Ll, Dd,
        sxh, sxl, LD, cxh, cxl, LD, lnum, nullptr, nullptr, LLm, nullptr, 0);
    cauchy_kernel<<<(unsigned)((Bz * LLm + 255) / 256), 256>>>(lnum, ss, cs, Ll);
    softmax_row_kernel<<<Bz * Ll, 256>>>(lnum, Ll);
    split_transpose<<<dim3(Ll / 32, Ll / 32, Bz), tb>>>(lnum, lsth, lstl, Ll, Ll);

    // ---------------- combine ----------------
    // T[d,l] = sum_d2 dscore[d,d2] * x_LD[l,d2] -> pair (DL layout)
    gemm_mma<2><<<dim3(Ll / 128, Dd / 128, Bz), 256, SMEMB>>>(Dd, Ll, Dd,
        dsph, dspl, DDm, xth, xtl, LD, nullptr, p1h, p1l, LD, nullptr, 0);
    // y[d,l2] = (sum_l1 T[d,l1] * lscoreT[l2,l1] + x) / 2
    gemm_mma<3><<<dim3(Ll / 128, Dd / 128, Bz), 256, SMEMB>>>(Dd, Ll, Ll,
        p1h, p1l, LD, lsth, lstl, LLm, out, nullptr, nullptr, LD, x, LD);
}

// round 9
// speedup vs baseline: 2.3102x; 1.4652x over previous
#include <cuda_runtime.h>
#include <cuda_fp16.h>
#include <cstdint>
#include <math.h>

#define Bz 8
#define Dd 1024
#define Ll 2048
#define CAUCHY_E 1.0100501670841680575f
#define PI_F 3.14159265358979323846f

typedef __half h16;

// ============================ device scratch ===============================
#define NLD ((size_t)Bz * Ll * Dd)
__device__ __align__(16) h16 g_wh[(size_t)12 * Dd * Dd], g_wl[(size_t)12 * Dd * Dd];
__device__ __align__(16) h16 g_xth[NLD], g_xtl[NLD];
__device__ __align__(16) h16 g_p1h[NLD], g_p1l[NLD];
__device__ __align__(16) h16 g_p2h[NLD], g_p2l[NLD];
__device__ __align__(16) h16 g_sxh[NLD], g_sxl[NLD];
__device__ __align__(16) h16 g_cxh[NLD], g_cxl[NLD];
__device__ __align__(16) h16 g_dsph[(size_t)Bz * Dd * Dd], g_dspl[(size_t)Bz * Dd * Dd];
__device__ __align__(16) h16 g_lsth[(size_t)Bz * Ll * Ll], g_lstl[(size_t)Bz * Ll * Ll];
__device__ __align__(16) float g_dnum[(size_t)Bz * Dd * Dd];
__device__ __align__(16) float g_lnum[(size_t)Bz * Ll * Ll];
__device__ float g_ss[(size_t)Bz * Ll], g_cs[(size_t)Bz * Ll];

// ============================= mma helpers =================================
__device__ __forceinline__ void mma16816(float* c, const uint32_t* a, const uint32_t* b) {
    asm volatile(
        "mma.sync.aligned.m16n8k16.row.col.f32.f16.f16.f32 "
        "{%0,%1,%2,%3}, {%4,%5,%6,%7}, {%8,%9}, {%0,%1,%2,%3};"
        : "+f"(c[0]), "+f"(c[1]), "+f"(c[2]), "+f"(c[3])
        : "r"(a[0]), "r"(a[1]), "r"(a[2]), "r"(a[3]), "r"(b[0]), "r"(b[1]));
}
__device__ __forceinline__ void ldsm_x4(uint32_t* r, uint32_t addr) {
    asm volatile("ldmatrix.sync.aligned.m8n8.x4.shared.b16 {%0,%1,%2,%3}, [%4];"
                 : "=r"(r[0]), "=r"(r[1]), "=r"(r[2]), "=r"(r[3]) : "r"(addr));
}
__device__ __forceinline__ uint32_t smem_u32(const void* p) {
    uint32_t a;
    asm("{ .reg .u64 t; cvta.to.shared.u64 t, %1; cvt.u32.u64 %0, t; }" : "=r"(a) : "l"(p));
    return a;
}
__device__ __forceinline__ void cp_async16(uint32_t d, const void* g) {
    asm volatile("cp.async.ca.shared.global [%0], [%1], 16;" :: "r"(d), "l"(g));
}

// ===========================================================================
// split-fp16 GEMM via mma.sync: C[b] = A[b] * B[b]^T
// A: MxK (K-major), B: NxK (K-major), (hi,lo) pairs; product = hh + hl + lh.
// CTA 128x256, 256 thr (8 warps: 2M x 4N, warp tile 64x64), K-chunk 32,
// 3-stage cp.async pipeline. Rows padded 64B->80B (conflict-free ldmatrix).
// EPI 0: fp32 out   EPI 1: h16 pair + bias[n]   EPI 2: h16 pair
// EPI 3: fp32 out = (acc + aux)/2
// ===========================================================================
#define ROWB 80
#define ABUF 10240            // 128 rows * 80B
#define BBUF 20480            // 256 rows * 80B
#define STAGEB 61440          // Ah | Al | Bh | Bl
#define NSTG 3
#define SMEMB (NSTG * STAGEB)

template <int EPI>
__global__ void __launch_bounds__(256, 1) gemm_mma(
    int M, int N, int K,
    const h16* __restrict__ Ah, const h16* __restrict__ Al, long sA,
    const h16* __restrict__ Bh, const h16* __restrict__ Bl, long sB,
    float* __restrict__ C, h16* __restrict__ Ch, h16* __restrict__ Cl, long sC,
    const float* __restrict__ aux, long sAux)
{
    extern __shared__ __align__(16) char smem[];
    const uint32_t su = smem_u32(smem);
    const int tid = threadIdx.x;
    const int wid = tid >> 5, lane = tid & 31;
    const int gid = lane >> 2, tig = lane & 3;
    const int warpM = wid >> 2, warpN = wid & 3;     // 2 x 4
    const int m0 = blockIdx.y * 128, n0 = blockIdx.x * 256, bz = blockIdx.z;

    const h16* pAh = Ah + (long)bz * sA;
    const h16* pAl = Al + (long)bz * sA;
    const h16* pBh = Bh + (long)bz * sB;
    const h16* pBl = Bl + (long)bz * sB;

    auto issue = [&](int stage, int k0) {
        const uint32_t sb = su + stage * STAGEB;
        #pragma unroll
        for (int t = 0; t < 12; ++t) {
            int idx = tid + t * 256;
            int r = idx >> 2, ch = idx & 3;
            const h16* g;
            uint32_t dst;
            if (r < 128) {
                g = pAh + (long)(m0 + r) * K + k0 + ch * 8;
                dst = sb + r * ROWB + ch * 16;
            } else if (r < 256) {
                int rr = r - 128;
                g = pAl + (long)(m0 + rr) * K + k0 + ch * 8;
                dst = sb + ABUF + rr * ROWB + ch * 16;
            } else if (r < 512) {
                int rr = r - 256;
                g = pBh + (long)(n0 + rr) * K + k0 + ch * 8;
                dst = sb + 2 * ABUF + rr * ROWB + ch * 16;
            } else {
                int rr = r - 512;
                g = pBl + (long)(n0 + rr) * K + k0 + ch * 8;
                dst = sb + 2 * ABUF + BBUF + rr * ROWB + ch * 16;
            }
            cp_async16(dst, g);
        }
    };

    float acc[4][8][4];
    #pragma unroll
    for (int i = 0; i < 4; i++)
        #pragma unroll
        for (int j = 0; j < 8; j++)
            #pragma unroll
            for (int q = 0; q < 4; q++) acc[i][j][q] = 0.f;

    const int nch = K >> 5;
    issue(0, 0);
    asm volatile("cp.async.commit_group;" ::: "memory");
    if (nch > 1) issue(1, 32);
    asm volatile("cp.async.commit_group;" ::: "memory");

    // per-lane fragment address components
    const int arow = lane & 15;
    const int acolx = (lane >> 4) * 8;                 // ldmatrix x4 A (16x16)
    const int brow = ((lane >> 4) & 1) * 8 + (lane & 7);
    const int bkoff = ((lane >> 3) & 1) * 8;           // ldmatrix x4 B (16 rows x 2 k-halves)

    for (int c = 0; c < nch; ++c) {
        if (c + 2 < nch) issue((c + 2) % NSTG, (c + 2) << 5);
        asm volatile("cp.async.commit_group;" ::: "memory");
        asm volatile("cp.async.wait_group 2;" ::: "memory");
        __syncthreads();

        const uint32_t sb = su + (c % NSTG) * STAGEB;
        #pragma unroll
        for (int kk = 0; kk < 32; kk += 16) {
            uint32_t ah[4][4], al[4][4];
            #pragma unroll
            for (int mt = 0; mt < 4; ++mt) {
                uint32_t ad = sb + (warpM * 64 + mt * 16 + arow) * ROWB + (kk + acolx) * 2;
                ldsm_x4(ah[mt], ad);
                ldsm_x4(al[mt], ad + ABUF);
            }
            #pragma unroll
            for (int h = 0; h < 2; ++h) {
                uint32_t bh[4][2], bl[4][2];
                #pragma unroll
                for (int p = 0; p < 2; ++p) {
                    uint32_t bd = sb + 2 * ABUF +
                                  (warpN * 64 + h * 32 + p * 16 + brow) * ROWB +
                                  (kk + bkoff) * 2;
                    uint32_t rh[4], rl[4];
                    ldsm_x4(rh, bd);
                    ldsm_x4(rl, bd + BBUF);
                    bh[p * 2][0] = rh[0]; bh[p * 2][1] = rh[1];
                    bh[p * 2 + 1][0] = rh[2]; bh[p * 2 + 1][1] = rh[3];
                    bl[p * 2][0] = rl[0]; bl[p * 2][1] = rl[1];
                    bl[p * 2 + 1][0] = rl[2]; bl[p * 2 + 1][1] = rl[3];
                }
                #pragma unroll
                for (int mt = 0; mt < 4; ++mt)
                    #pragma unroll
                    for (int q = 0; q < 4; ++q) {
                        float* a = acc[mt][h * 4 + q];
                        mma16816(a, ah[mt], bh[q]);   // hh
                        mma16816(a, ah[mt], bl[q]);   // hl
                        mma16816(a, al[mt], bh[q]);   // lh
                    }
            }
        }
        __syncthreads();
    }

    // ------------------------------ epilogue ------------------------------
    #pragma unroll
    for (int mt = 0; mt < 4; ++mt) {
        const int r0 = m0 + warpM * 64 + mt * 16 + gid;
        #pragma unroll
        for (int nt = 0; nt < 8; ++nt) {
            const int cc = n0 + warpN * 64 + nt * 8 + tig * 2;
            float* a = acc[mt][nt];
            if (EPI == 0) {
                float* cp = C + (long)bz * sC;
                *(float2*)(cp + (long)r0 * N + cc)       = make_float2(a[0], a[1]);
                *(float2*)(cp + (long)(r0 + 8) * N + cc) = make_float2(a[2], a[3]);
            } else if (EPI == 1 || EPI == 2) {
                float v0 = a[0], v1 = a[1], v2 = a[2], v3 = a[3];
                if (EPI == 1) {
                    float b0 = aux[cc], b1 = aux[cc + 1];
                    v0 += b0; v1 += b1; v2 += b0; v3 += b1;
                }
                h16* hp = Ch + (long)bz * sC;
                h16* lp = Cl + (long)bz * sC;
                h16 h0 = __float2half_rn(v0), h1 = __float2half_rn(v1);
                h16 h2 = __float2half_rn(v2), h3 = __float2half_rn(v3);
                *(__half2*)(hp + (long)r0 * N + cc) = __halves2half2(h0, h1);
                *(__half2*)(hp + (long)(r0 + 8) * N + cc) = __halves2half2(h2, h3);
                *(__half2*)(lp + (long)r0 * N + cc) = __halves2half2(
                    __float2half_rn(v0 - __half2float(h0)), __float2half_rn(v1 - __half2float(h1)));
                *(__half2*)(lp + (long)(r0 + 8) * N + cc) = __halves2half2(
                    __float2half_rn(v2 - __half2float(h2)), __float2half_rn(v3 - __half2float(h3)));
            } else {
                const float* xp = aux + (long)bz * sAux;
                float* cp = C + (long)bz * sC;
                float2 x0 = *(const float2*)(xp + (long)r0 * N + cc);
                float2 x1 = *(const float2*)(xp + (long)(r0 + 8) * N + cc);
                *(float2*)(cp + (long)r0 * N + cc) =
                    make_float2((a[0] + x0.x) * 0.5f, (a[1] + x0.y) * 0.5f);
                *(float2*)(cp + (long)(r0 + 8) * N + cc) =
                    make_float2((a[2] + x1.x) * 0.5f, (a[3] + x1.y) * 0.5f);
            }
        }
    }
}

// ========================= conversions / pointwise =========================
__global__ void split_kernel(const float4* __restrict__ in,
                             __half2* __restrict__ h2, __half2* __restrict__ l2, long n4) {
    long i = (long)blockIdx.x * blockDim.x + threadIdx.x;
    if (i >= n4) return;
    float4 v = in[i];
    h16 ha = __float2half_rn(v.x), hb = __float2half_rn(v.y);
    h16 hc = __float2half_rn(v.z), hd = __float2half_rn(v.w);
    h2[2 * i]     = __halves2half2(ha, hb);
    h2[2 * i + 1] = __halves2half2(hc, hd);
    l2[2 * i]     = __halves2half2(__float2half_rn(v.x - __half2float(ha)),
                                   __float2half_rn(v.y - __half2float(hb)));
    l2[2 * i + 1] = __halves2half2(__float2half_rn(v.z - __half2float(hc)),
                                   __float2half_rn(v.w - __half2float(hd)));
}

// fp32 [z][R][C] -> (hi,lo) h16 [z][C][R]
__global__ void split_transpose(const float* __restrict__ in,
                                h16* __restrict__ oh, h16* __restrict__ ol, int R, int C) {
    __shared__ float t[32][33];
    const long ob = (long)blockIdx.z * R * C;
    int r0 = blockIdx.y * 32, c0 = blockIdx.x * 32;
    int tx = threadIdx.x, ty = threadIdx.y;
    #pragma unroll
    for (int i = 0; i < 4; i++)
        t[ty + i * 8][tx] = in[ob + (long)(r0 + ty + i * 8) * C + c0 + tx];
    __syncthreads();
    #pragma unroll
    for (int i = 0; i < 4; i++) {
        int oc = c0 + ty + i * 8;
        float v = t[tx][ty + i * 8];
        h16 h = __float2half_rn(v);
        oh[ob + (long)oc * R + r0 + tx] = h;
        ol[ob + (long)oc * R + r0 + tx] = __float2half_rn(v - __half2float(h));
    }
}

// 16-bit [z][R][C] -> [z][C][R] (bit-exact move)
__global__ void transpose_u16(const unsigned short* __restrict__ in,
                              unsigned short* __restrict__ out, int R, int C) {
    __shared__ unsigned short t[32][34];
    const long ob = (long)blockIdx.z * R * C;
    int r0 = blockIdx.y * 32, c0 = blockIdx.x * 32;
    int tx = threadIdx.x, ty = threadIdx.y;
    #pragma unroll
    for (int i = 0; i < 4; i++)
        t[ty + i * 8][tx] = in[ob + (long)(r0 + ty + i * 8) * C + c0 + tx];
    __syncthreads();
    #pragma unroll
    for (int i = 0; i < 4; i++)
        out[ob + (long)(c0 + ty + i * 8) * R + r0 + tx] = t[tx][ty + i * 8];
}

__device__ __forceinline__ float blockReduceSum(float v) {
    __shared__ float sm[32];
    __syncthreads();
    int lane = threadIdx.x & 31, w = threadIdx.x >> 5;
    #pragma unroll
    for (int o = 16; o; o >>= 1) v += __shfl_down_sync(0xffffffffu, v, o);
    if (!lane) sm[w] = v;
    __syncthreads();
    int nw = blockDim.x >> 5;
    v = (threadIdx.x < nw) ? sm[threadIdx.x] : 0.f;
    if (w == 0) {
        #pragma unroll
        for (int o = 16; o; o >>= 1) v += __shfl_down_sync(0xffffffffu, v, o);
        if (!lane) sm[0] = v;
    }
    __syncthreads();
    return sm[0];
}
__device__ __forceinline__ float blockReduceMax(float v) {
    __shared__ float sm[32];
    __syncthreads();
    int lane = threadIdx.x & 31, w = threadIdx.x >> 5;
    #pragma unroll
    for (int o = 16; o; o >>= 1) v = fmaxf(v, __shfl_down_sync(0xffffffffu, v, o));
    if (!lane) sm[w] = v;
    __syncthreads();
    int nw = blockDim.x >> 5;
    v = (threadIdx.x < nw) ? sm[threadIdx.x] : -1e30f;
    if (w == 0) {
        #pragma unroll
        for (int o = 16; o; o >>= 1) v = fmaxf(v, __shfl_down_sync(0xffffffffu, v, o));
        if (!lane) sm[0] = v;
    }
    __syncthreads();
    return sm[0];
}

// per-row sum of (hi+lo)^2, contiguous length C; one block per row
__global__ void sumsq_row_pair(const h16* __restrict__ h, const h16* __restrict__ l,
                               float* __restrict__ out, int C) {
    long row = blockIdx.x;
    const h16* hp = h + row * (long)C;
    const h16* lp = l + row * (long)C;
    float s = 0.f;
    for (int i = threadIdx.x; i < C; i += blockDim.x) {
        float v = __half2float(hp[i]) + __half2float(lp[i]);
        s = fmaf(v, v, s);
    }
    s = blockReduceSum(s);
    if (threadIdx.x == 0) out[row] = s;
}

__global__ void cauchy_kernel(float* __restrict__ S, const float* __restrict__ ss,
                              const float* __restrict__ cs, int M) {
    long idx = (long)blockIdx.x * blockDim.x + threadIdx.x;
    long total = (long)Bz * M * M;
    if (idx >= total) return;
    int c = (int)(idx % M);
    int r = (int)((idx / M) % M);
    int b = (int)(idx / ((long)M * M));
    float mm = S[idx];
    float v = (mm * mm) / (ss[(long)b * M + r] * cs[(long)b * M + c]);
    float p = __powf(v, CAUCHY_E);
    if (r == c) p -= 1.0f;
    float o = 0.5f - 0.5f * __cosf(p * PI_F);
    S[idx] = fmaxf(o, 0.0f);
}

// softmax over rows (axis 1) of (B, M, M): thread per column
__global__ void softmax_col_kernel(float* __restrict__ S, int M) {
    int n = blockIdx.x * blockDim.x + threadIdx.x;
    int b = blockIdx.z;
    float* base = S + (long)b * M * M + n;
    float mx = -1e30f;
    for (int m = 0; m < M; m++) mx = fmaxf(mx, base[(long)m * M]);
    float s = 0.f;
    for (int m = 0; m < M; m++) {
        float e = __expf(base[(long)m * M] - mx);
        base[(long)m * M] = e;
        s += e;
    }
    float inv = 1.0f / s;
    for (int m = 0; m < M; m++) base[(long)m * M] *= inv;
}

// softmax over last axis; one block per row
__global__ void softmax_row_kernel(float* __restrict__ S, int n) {
    float* p = S + (long)blockIdx.x * n;
    float mx = -1e30f;
    for (int i = threadIdx.x; i < n; i += blockDim.x) mx = fmaxf(mx, p[i]);
    mx = blockReduceMax(mx);
    float s = 0.f;
    for (int i = threadIdx.x; i < n; i += blockDim.x) {
        float e = __expf(p[i] - mx);
        p[i] = e;
        s += e;
    }
    s = blockReduceSum(s);
    float inv = 1.0f / s;
    for (int i = threadIdx.x; i < n; i += blockDim.x) p[i] *= inv;
}

// ============================= orchestration ===============================
extern "C" void kernel_launch(void* const* d_in, const int* in_sizes, int n_in,
                              void* d_out, int out_size) {
    (void)in_sizes; (void)n_in; (void)out_size;
    const float* x = (const float*)d_in[0];
    const float* W[4] = {(const float*)d_in[1], (const float*)d_in[3],
                         (const float*)d_in[5], (const float*)d_in[7]};
    const float* bb[4] = {(const float*)d_in[2], (const float*)d_in[4],
                          (const float*)d_in[6], (const float*)d_in[8]};
    float* out = (float*)d_out;

    h16 *wh, *wl, *xth, *xtl, *p1h, *p1l, *p2h, *p2l, *sxh, *sxl, *cxh, *cxl;
    h16 *dsph, *dspl, *lsth, *lstl;
    float *dnum, *lnum, *ss, *cs;
    cudaGetSymbolAddress((void**)&wh, g_wh);   cudaGetSymbolAddress((void**)&wl, g_wl);
    cudaGetSymbolAddress((void**)&xth, g_xth); cudaGetSymbolAddress((void**)&xtl, g_xtl);
    cudaGetSymbolAddress((void**)&p1h, g_p1h); cudaGetSymbolAddress((void**)&p1l, g_p1l);
    cudaGetSymbolAddress((void**)&p2h, g_p2h); cudaGetSymbolAddress((void**)&p2l, g_p2l);
    cudaGetSymbolAddress((void**)&sxh, g_sxh); cudaGetSymbolAddress((void**)&sxl, g_sxl);
    cudaGetSymbolAddress((void**)&cxh, g_cxh); cudaGetSymbolAddress((void**)&cxl, g_cxl);
    cudaGetSymbolAddress((void**)&dsph, g_dsph); cudaGetSymbolAddress((void**)&dspl, g_dspl);
    cudaGetSymbolAddress((void**)&lsth, g_lsth); cudaGetSymbolAddress((void**)&lstl, g_lstl);
    cudaGetSymbolAddress((void**)&dnum, g_dnum); cudaGetSymbolAddress((void**)&lnum, g_lnum);
    cudaGetSymbolAddress((void**)&ss, g_ss);   cudaGetSymbolAddress((void**)&cs, g_cs);

    cudaFuncSetAttribute(gemm_mma<0>, cudaFuncAttributeMaxDynamicSharedMemorySize, SMEMB);
    cudaFuncSetAttribute(gemm_mma<1>, cudaFuncAttributeMaxDynamicSharedMemorySize, SMEMB);
    cudaFuncSetAttribute(gemm_mma<2>, cudaFuncAttributeMaxDynamicSharedMemorySize, SMEMB);
    cudaFuncSetAttribute(gemm_mma<3>, cudaFuncAttributeMaxDynamicSharedMemorySize, SMEMB);

    const long LD = (long)Ll * Dd;
    const long DDm = (long)Dd * Dd;
    const long LLm = (long)Ll * Ll;
    const dim3 tb(32, 8);

    // ---- input conversions ----
    for (int i = 0; i < 4; i++) {
        long n4 = 3L * Dd * Dd / 4;
        split_kernel<<<(unsigned)((n4 + 255) / 256), 256>>>(
            (const float4*)W[i],
            (__half2*)(wh + (size_t)i * 3 * Dd * Dd),
            (__half2*)(wl + (size_t)i * 3 * Dd * Dd), n4);
    }
    split_transpose<<<dim3(Ll / 32, Dd / 32, Bz), tb>>>(x, xth, xtl, Dd, Ll);  // x -> LD pair

    // ---- 3-layer pointwise MLP in LD layout ----
    const dim3 gM(Dd / 256, Ll / 128, Bz);
    auto mlp = [&](int wi, const float* bias, h16* oh, h16* ol) {
        const h16* wph = wh + (size_t)wi * 3 * Dd * Dd;
        const h16* wpl = wl + (size_t)wi * 3 * Dd * Dd;
        gemm_mma<1><<<gM, 256, SMEMB>>>(Ll, Dd, Dd, xth, xtl, LD, wph, wpl, 0,
                                        nullptr, p1h, p1l, LD, bias, 0);
        gemm_mma<1><<<gM, 256, SMEMB>>>(Ll, Dd, Dd, p1h, p1l, LD, wph + DDm, wpl + DDm, 0,
                                        nullptr, p2h, p2l, LD, bias + Dd, 0);
        gemm_mma<1><<<gM, 256, SMEMB>>>(Ll, Dd, Dd, p2h, p2l, LD, wph + 2 * DDm, wpl + 2 * DDm, 0,
                                        nullptr, oh, ol, LD, bias + 2 * Dd, 0);
    };

    // ---------------- dscore branch ----------------
    mlp(0, bb[0], sxh, sxl);   // dsx (LD)
    mlp(1, bb[1], cxh, cxl);   // dcx (LD)
    transpose_u16<<<dim3(Dd / 32, Ll / 32, Bz), tb>>>((const unsigned short*)sxh, (unsigned short*)p1h, Ll, Dd);
    transpose_u16<<<dim3(Dd / 32, Ll / 32, Bz), tb>>>((const unsigned short*)sxl, (unsigned short*)p1l, Ll, Dd);
    transpose_u16<<<dim3(Dd / 32, Ll / 32, Bz), tb>>>((const unsigned short*)cxh, (unsigned short*)p2h, Ll, Dd);
    transpose_u16<<<dim3(Dd / 32, Ll / 32, Bz), tb>>>((const unsigned short*)cxl, (unsigned short*)p2l, Ll, Dd);
    sumsq_row_pair<<<Bz * Dd, 256>>>(p1h, p1l, ss, Ll);
    sumsq_row_pair<<<Bz * Dd, 256>>>(p2h, p2l, cs, Ll);
    gemm_mma<0><<<dim3(Dd / 256, Dd / 128, Bz), 256, SMEMB>>>(Dd, Dd, Ll,
        p1h, p1l, LD, p2h, p2l, LD, dnum, nullptr, nullptr, DDm, nullptr, 0);
    cauchy_kernel<<<(unsigned)((Bz * DDm + 255) / 256), 256>>>(dnum, ss, cs, Dd);
    softmax_col_kernel<<<dim3(Dd / 256, 1, Bz), 256>>>(dnum, Dd);
    split_kernel<<<(unsigned)((Bz * DDm / 4 + 255) / 256), 256>>>(
        (const float4*)dnum, (__half2*)dsph, (__half2*)dspl, Bz * DDm / 4);

    // ---------------- lscore branch ----------------
    mlp(2, bb[2], sxh, sxl);   // lsx (LD)
    mlp(3, bb[3], cxh, cxl);   // lcx (LD)
    sumsq_row_pair<<<Bz * Ll, 256>>>(sxh, sxl, ss, Dd);
    sumsq_row_pair<<<Bz * Ll, 256>>>(cxh, cxl, cs, Dd);
    gemm_mma<0><<<dim3(Ll / 256, Ll / 128, Bz), 256, SMEMB>>>(Ll, Ll, Dd,
        sxh, sxl, LD, cxh, cxl, LD, lnum, nullptr, nullptr, LLm, nullptr, 0);
    cauchy_kernel<<<(unsigned)((Bz * LLm + 255) / 256), 256>>>(lnum, ss, cs, Ll);
    softmax_row_kernel<<<Bz * Ll, 256>>>(lnum, Ll);
    split_transpose<<<dim3(Ll / 32, Ll / 32, Bz), tb>>>(lnum, lsth, lstl, Ll, Ll);

    // ---------------- combine ----------------
    // T[d,l] = sum_d2 dscore[d,d2] * x_LD[l,d2] -> pair (DL layout)
    gemm_mma<2><<<dim3(Ll / 256, Dd / 128, Bz), 256, SMEMB>>>(Dd, Ll, Dd,
        dsph, dspl, DDm, xth, xtl, LD, nullptr, p1h, p1l, LD, nullptr, 0);
    // y[d,l2] = (sum_l1 T[d,l1] * lscoreT[l2,l1] + x) / 2
    gemm_mma<3><<<dim3(Ll / 256, Dd / 128, Bz), 256, SMEMB>>>(Dd, Ll, Ll,
        p1h, p1l, LD, lsth, lstl, LLm, out, nullptr, nullptr, LD, x, LD);
}

// round 13
// speedup vs baseline: 3.6789x; 1.5925x over previous
#include <cuda_runtime.h>
#include <cuda_fp16.h>
#include <cstdint>
#include <math.h>

#define Bz 8
#define Dd 1024
#define Ll 2048
#define CAUCHY_E 1.0100501670841680575f
#define PI_F 3.14159265358979323846f

typedef __half h16;

// ============================ device scratch ===============================
#define NLD ((size_t)Bz * Ll * Dd)
__device__ __align__(16) h16 g_wh[(size_t)12 * Dd * Dd];
__device__ __align__(16) h16 g_xth[NLD], g_xtl[NLD];
__device__ __align__(16) h16 g_p1h[NLD], g_p1l[NLD];
__device__ __align__(16) h16 g_p2h[NLD], g_p2l[NLD];
__device__ __align__(16) h16 g_sxh[NLD], g_sxl[NLD];
__device__ __align__(16) h16 g_cxh[NLD], g_cxl[NLD];
__device__ __align__(16) h16 g_dsph[(size_t)Bz * Dd * Dd], g_dspl[(size_t)Bz * Dd * Dd];
__device__ __align__(16) h16 g_lsth[(size_t)Bz * Ll * Ll], g_lstl[(size_t)Bz * Ll * Ll];
__device__ __align__(16) float g_dnum[(size_t)Bz * Dd * Dd];
__device__ __align__(16) float g_lnum[(size_t)Bz * Ll * Ll];
__device__ float g_ss[(size_t)Bz * Ll], g_cs[(size_t)Bz * Ll];

// ============================= mma helpers =================================
__device__ __forceinline__ void mma16816(float* c, const uint32_t* a, const uint32_t* b) {
    asm volatile(
        "mma.sync.aligned.m16n8k16.row.col.f32.f16.f16.f32 "
        "{%0,%1,%2,%3}, {%4,%5,%6,%7}, {%8,%9}, {%0,%1,%2,%3};"
        : "+f"(c[0]), "+f"(c[1]), "+f"(c[2]), "+f"(c[3])
        : "r"(a[0]), "r"(a[1]), "r"(a[2]), "r"(a[3]), "r"(b[0]), "r"(b[1]));
}
__device__ __forceinline__ void ldsm_x4(uint32_t* r, uint32_t addr) {
    asm volatile("ldmatrix.sync.aligned.m8n8.x4.shared.b16 {%0,%1,%2,%3}, [%4];"
                 : "=r"(r[0]), "=r"(r[1]), "=r"(r[2]), "=r"(r[3]) : "r"(addr));
}
__device__ __forceinline__ uint32_t smem_u32(const void* p) {
    uint32_t a;
    asm("{ .reg .u64 t; cvta.to.shared.u64 t, %1; cvt.u32.u64 %0, t; }" : "=r"(a) : "l"(p));
    return a;
}
__device__ __forceinline__ void cp_async16(uint32_t d, const void* g) {
    asm volatile("cp.async.ca.shared.global [%0], [%1], 16;" :: "r"(d), "l"(g));
}

// ===========================================================================
// 2-term split-fp16 GEMM via mma.sync: C[b] = (Ah + Al) * Bh^T  (hh + lh)
// A: MxK (K-major) hi/lo pair, B: NxK (K-major) hi only.
// CTA 128x256, 256 thr (8 warps: 2M x 4N, warp tile 64x64), K-chunk 32,
// 4-stage cp.async pipeline, single __syncthreads per chunk.
// Rows padded 64B->80B (conflict-free ldmatrix).
// EPI 0: fp32 out   EPI 1: h16 pair + bias[n]   EPI 2: h16 pair
// EPI 3: fp32 out = (acc + aux)/2
// ===========================================================================
#define ROWB 80
#define ABUF 10240            // 128 rows * 80B
#define BBUF 20480            // 256 rows * 80B
#define STAGEB 40960          // Ah | Al | Bh
#define NSTG 4
#define SMEMB (NSTG * STAGEB)

template <int EPI>
__global__ void __launch_bounds__(256, 1) gemm_mma(
    int M, int N, int K,
    const h16* __restrict__ Ah, const h16* __restrict__ Al, long sA,
    const h16* __restrict__ Bh, long sB,
    float* __restrict__ C, h16* __restrict__ Ch, h16* __restrict__ Cl, long sC,
    const float* __restrict__ aux, long sAux)
{
    extern __shared__ __align__(16) char smem[];
    const uint32_t su = smem_u32(smem);
    const int tid = threadIdx.x;
    const int wid = tid >> 5, lane = tid & 31;
    const int gid = lane >> 2, tig = lane & 3;
    const int warpM = wid >> 2, warpN = wid & 3;     // 2 x 4
    const int m0 = blockIdx.y * 128, n0 = blockIdx.x * 256, bz = blockIdx.z;

    const h16* pAh = Ah + (long)bz * sA;
    const h16* pAl = Al + (long)bz * sA;
    const h16* pBh = Bh + (long)bz * sB;

    auto issue = [&](int stage, int k0) {
        const uint32_t sb = su + stage * STAGEB;
        #pragma unroll
        for (int t = 0; t < 8; ++t) {               // 512 rows * 4 chunks / 256 thr
            int idx = tid + t * 256;
            int r = idx >> 2, ch = idx & 3;
            const h16* g;
            uint32_t dst;
            if (r < 128) {
                g = pAh + (long)(m0 + r) * K + k0 + ch * 8;
                dst = sb + r * ROWB + ch * 16;
            } else if (r < 256) {
                int rr = r - 128;
                g = pAl + (long)(m0 + rr) * K + k0 + ch * 8;
                dst = sb + ABUF + rr * ROWB + ch * 16;
            } else {
                int rr = r - 256;                   // 0..255 -> B rows
                g = pBh + (long)(n0 + rr) * K + k0 + ch * 8;
                dst = sb + 2 * ABUF + rr * ROWB + ch * 16;
            }
            cp_async16(dst, g);
        }
    };

    float acc[4][8][4];
    #pragma unroll
    for (int i = 0; i < 4; i++)
        #pragma unroll
        for (int j = 0; j < 8; j++)
            #pragma unroll
            for (int q = 0; q < 4; q++) acc[i][j][q] = 0.f;

    const int nch = K >> 5;
    issue(0, 0);
    asm volatile("cp.async.commit_group;" ::: "memory");
    if (nch > 1) issue(1, 32);
    asm volatile("cp.async.commit_group;" ::: "memory");

    const int arow = lane & 15;
    const int acolx = (lane >> 4) * 8;
    const int brow = ((lane >> 4) & 1) * 8 + (lane & 7);
    const int bkoff = ((lane >> 3) & 1) * 8;

    for (int c = 0; c < nch; ++c) {
        if (c + 2 < nch) issue((c + 2) % NSTG, (c + 2) << 5);
        asm volatile("cp.async.commit_group;" ::: "memory");
        asm volatile("cp.async.wait_group 2;" ::: "memory");
        __syncthreads();

        const uint32_t sb = su + (c % NSTG) * STAGEB;
        #pragma unroll
        for (int kk = 0; kk < 32; kk += 16) {
            uint32_t ah[4][4], al[4][4];
            #pragma unroll
            for (int mt = 0; mt < 4; ++mt) {
                uint32_t ad = sb + (warpM * 64 + mt * 16 + arow) * ROWB + (kk + acolx) * 2;
                ldsm_x4(ah[mt], ad);
                ldsm_x4(al[mt], ad + ABUF);
            }
            #pragma unroll
            for (int h = 0; h < 2; ++h) {
                uint32_t bh[4][2];
                #pragma unroll
                for (int p = 0; p < 2; ++p) {
                    uint32_t bd = sb + 2 * ABUF +
                                  (warpN * 64 + h * 32 + p * 16 + brow) * ROWB +
                                  (kk + bkoff) * 2;
                    uint32_t rh[4];
                    ldsm_x4(rh, bd);
                    bh[p * 2][0] = rh[0]; bh[p * 2][1] = rh[1];
                    bh[p * 2 + 1][0] = rh[2]; bh[p * 2 + 1][1] = rh[3];
                }
                #pragma unroll
                for (int mt = 0; mt < 4; ++mt)
                    #pragma unroll
                    for (int q = 0; q < 4; ++q) {
                        float* a = acc[mt][h * 4 + q];
                        mma16816(a, ah[mt], bh[q]);   // hh
                        mma16816(a, al[mt], bh[q]);   // lh
                    }
            }
        }
        // no trailing sync needed: warp skew < 1 iteration, and the stage
        // written at iteration c+1 ((c+3)%4) never equals the stage read at c.
    }

    // ------------------------------ epilogue ------------------------------
    #pragma unroll
    for (int mt = 0; mt < 4; ++mt) {
        const int r0 = m0 + warpM * 64 + mt * 16 + gid;
        #pragma unroll
        for (int nt = 0; nt < 8; ++nt) {
            const int cc = n0 + warpN * 64 + nt * 8 + tig * 2;
            float* a = acc[mt][nt];
            if (EPI == 0) {
                float* cp = C + (long)bz * sC;
                *(float2*)(cp + (long)r0 * N + cc)       = make_float2(a[0], a[1]);
                *(float2*)(cp + (long)(r0 + 8) * N + cc) = make_float2(a[2], a[3]);
            } else if (EPI == 1 || EPI == 2) {
                float v0 = a[0], v1 = a[1], v2 = a[2], v3 = a[3];
                if (EPI == 1) {
                    float b0 = aux[cc], b1 = aux[cc + 1];
                    v0 += b0; v1 += b1; v2 += b0; v3 += b1;
                }
                h16* hp = Ch + (long)bz * sC;
                h16* lp = Cl + (long)bz * sC;
                h16 h0 = __float2half_rn(v0), h1 = __float2half_rn(v1);
                h16 h2 = __float2half_rn(v2), h3 = __float2half_rn(v3);
                *(__half2*)(hp + (long)r0 * N + cc) = __halves2half2(h0, h1);
                *(__half2*)(hp + (long)(r0 + 8) * N + cc) = __halves2half2(h2, h3);
                *(__half2*)(lp + (long)r0 * N + cc) = __halves2half2(
                    __float2half_rn(v0 - __half2float(h0)), __float2half_rn(v1 - __half2float(h1)));
                *(__half2*)(lp + (long)(r0 + 8) * N + cc) = __halves2half2(
                    __float2half_rn(v2 - __half2float(h2)), __float2half_rn(v3 - __half2float(h3)));
            } else {
                const float* xp = aux + (long)bz * sAux;
                float* cp = C + (long)bz * sC;
                float2 x0 = *(const float2*)(xp + (long)r0 * N + cc);
                float2 x1 = *(const float2*)(xp + (long)(r0 + 8) * N + cc);
                *(float2*)(cp + (long)r0 * N + cc) =
                    make_float2((a[0] + x0.x) * 0.5f, (a[1] + x0.y) * 0.5f);
                *(float2*)(cp + (long)(r0 + 8) * N + cc) =
                    make_float2((a[2] + x1.x) * 0.5f, (a[3] + x1.y) * 0.5f);
            }
        }
    }
}

// ========================= conversions / pointwise =========================
// l2 may be nullptr (hi-only split, e.g. weights)
__global__ void split_kernel(const float4* __restrict__ in,
                             __half2* __restrict__ h2, __half2* __restrict__ l2, long n4) {
    long i = (long)blockIdx.x * blockDim.x + threadIdx.x;
    if (i >= n4) return;
    float4 v = in[i];
    h16 ha = __float2half_rn(v.x), hb = __float2half_rn(v.y);
    h16 hc = __float2half_rn(v.z), hd = __float2half_rn(v.w);
    h2[2 * i]     = __halves2half2(ha, hb);
    h2[2 * i + 1] = __halves2half2(hc, hd);
    if (l2) {
        l2[2 * i]     = __halves2half2(__float2half_rn(v.x - __half2float(ha)),
                                       __float2half_rn(v.y - __half2float(hb)));
        l2[2 * i + 1] = __halves2half2(__float2half_rn(v.z - __half2float(hc)),
                                       __float2half_rn(v.w - __half2float(hd)));
    }
}

// fp32 [z][R][C] -> (hi,lo) h16 [z][C][R]
__global__ void split_transpose(const float* __restrict__ in,
                                h16* __restrict__ oh, h16* __restrict__ ol, int R, int C) {
    __shared__ float t[32][33];
    const long ob = (long)blockIdx.z * R * C;
    int r0 = blockIdx.y * 32, c0 = blockIdx.x * 32;
    int tx = threadIdx.x, ty = threadIdx.y;
    #pragma unroll
    for (int i = 0; i < 4; i++)
        t[ty + i * 8][tx] = in[ob + (long)(r0 + ty + i * 8) * C + c0 + tx];
    __syncthreads();
    #pragma unroll
    for (int i = 0; i < 4; i++) {
        int oc = c0 + ty + i * 8;
        float v = t[tx][ty + i * 8];
        h16 h = __float2half_rn(v);
        oh[ob + (long)oc * R + r0 + tx] = h;
        ol[ob + (long)oc * R + r0 + tx] = __float2half_rn(v - __half2float(h));
    }
}

// 16-bit [z][R][C] -> [z][C][R] (bit-exact move)
__global__ void transpose_u16(const unsigned short* __restrict__ in,
                              unsigned short* __restrict__ out, int R, int C) {
    __shared__ unsigned short t[32][34];
    const long ob = (long)blockIdx.z * R * C;
    int r0 = blockIdx.y * 32, c0 = blockIdx.x * 32;
    int tx = threadIdx.x, ty = threadIdx.y;
    #pragma unroll
    for (int i = 0; i < 4; i++)
        t[ty + i * 8][tx] = in[ob + (long)(r0 + ty + i * 8) * C + c0 + tx];
    __syncthreads();
    #pragma unroll
    for (int i = 0; i < 4; i++)
        out[ob + (long)(c0 + ty + i * 8) * R + r0 + tx] = t[tx][ty + i * 8];
}

__device__ __forceinline__ float blockReduceSum(float v) {
    __shared__ float sm[32];
    __syncthreads();
    int lane = threadIdx.x & 31, w = threadIdx.x >> 5;
    #pragma unroll
    for (int o = 16; o; o >>= 1) v += __shfl_down_sync(0xffffffffu, v, o);
    if (!lane) sm[w] = v;
    __syncthreads();
    int nw = blockDim.x >> 5;
    v = (threadIdx.x < nw) ? sm[threadIdx.x] : 0.f;
    if (w == 0) {
        #pragma unroll
        for (int o = 16; o; o >>= 1) v += __shfl_down_sync(0xffffffffu, v, o);
        if (!lane) sm[0] = v;
    }
    __syncthreads();
    return sm[0];
}
__device__ __forceinline__ float blockReduceMax(float v) {
    __shared__ float sm[32];
    __syncthreads();
    int lane = threadIdx.x & 31, w = threadIdx.x >> 5;
    #pragma unroll
    for (int o = 16; o; o >>= 1) v = fmaxf(v, __shfl_down_sync(0xffffffffu, v, o));
    if (!lane) sm[w] = v;
    __syncthreads();
    int nw = blockDim.x >> 5;
    v = (threadIdx.x < nw) ? sm[threadIdx.x] : -1e30f;
    if (w == 0) {
        #pragma unroll
        for (int o = 16; o; o >>= 1) v = fmaxf(v, __shfl_down_sync(0xffffffffu, v, o));
        if (!lane) sm[0] = v;
    }
    __syncthreads();
    return sm[0];
}

// per-row sum of (hi+lo)^2, contiguous length C; one block per row
__global__ void sumsq_row_pair(const h16* __restrict__ h, const h16* __restrict__ l,
                               float* __restrict__ out, int C) {
    long row = blockIdx.x;
    const h16* hp = h + row * (long)C;
    const h16* lp = l + row * (long)C;
    float s = 0.f;
    for (int i = threadIdx.x; i < C; i += blockDim.x) {
        float v = __half2float(hp[i]) + __half2float(lp[i]);
        s = fmaf(v, v, s);
    }
    s = blockReduceSum(s);
    if (threadIdx.x == 0) out[row] = s;
}

// fused: lscore row = softmax(relu(cauchy(lnum row))) -> h16 row-major
// one block (256 thr) per row of length Ll (8 elems/thread)
__global__ void cauchy_softmax_row_h16(const float* __restrict__ S,
                                       const float* __restrict__ ss,
                                       const float* __restrict__ cs,
                                       h16* __restrict__ outh, int M) {
    const long row = blockIdx.x;
    const int b = (int)(row / M), r = (int)(row % M);
    const float* p = S + row * (long)M;
    const float ssr = ss[(long)b * M + r];
    const float* csb = cs + (long)b * M;
    float v[8];
    float mx = -1e30f;
    #pragma unroll
    for (int i = 0; i < 8; i++) {
        int cidx = threadIdx.x + i * 256;
        float mm = p[cidx];
        float q = (mm * mm) / (ssr * csb[cidx]);
        float pw = __powf(q, CAUCHY_E);
        if (cidx == r) pw -= 1.0f;
        float o = 0.5f - 0.5f * __cosf(pw * PI_F);
        o = fmaxf(o, 0.0f);
        v[i] = o;
        mx = fmaxf(mx, o);
    }
    mx = blockReduceMax(mx);
    float s = 0.f;
    #pragma unroll
    for (int i = 0; i < 8; i++) { v[i] = __expf(v[i] - mx); s += v[i]; }
    s = blockReduceSum(s);
    float inv = 1.0f / s;
    #pragma unroll
    for (int i = 0; i < 8; i++)
        outh[row * (long)M + threadIdx.x + i * 256] = __float2half_rn(v[i] * inv);
}

__global__ void cauchy_kernel(float* __restrict__ S, const float* __restrict__ ss,
                              const float* __restrict__ cs, int M) {
    long idx = (long)blockIdx.x * blockDim.x + threadIdx.x;
    long total = (long)Bz * M * M;
    if (idx >= total) return;
    int c = (int)(idx % M);
    int r = (int)((idx / M) % M);
    int b = (int)(idx / ((long)M * M));
    float mm = S[idx];
    float v = (mm * mm) / (ss[(long)b * M + r] * cs[(long)b * M + c]);
    float p = __powf(v, CAUCHY_E);
    if (r == c) p -= 1.0f;
    float o = 0.5f - 0.5f * __cosf(p * PI_F);
    S[idx] = fmaxf(o, 0.0f);
}

// softmax over axis 1 of (B, M, M), thread per column; final pass writes h16 pair
__global__ void softmax_col_split(float* __restrict__ S,
                                  h16* __restrict__ hp, h16* __restrict__ lp, int M) {
    int n = blockIdx.x * blockDim.x + threadIdx.x;
    int b = blockIdx.z;
    const long ob = (long)b * M * M;
    float* base = S + ob + n;
    float mx = -1e30f;
    for (int m = 0; m < M; m++) mx = fmaxf(mx, base[(long)m * M]);
    float s = 0.f;
    for (int m = 0; m < M; m++) {
        float e = __expf(base[(long)m * M] - mx);
        base[(long)m * M] = e;
        s += e;
    }
    float inv = 1.0f / s;
    for (int m = 0; m < M; m++) {
        float v = base[(long)m * M] * inv;
        h16 h = __float2half_rn(v);
        hp[ob + (long)m * M + n] = h;
        lp[ob + (long)m * M + n] = __float2half_rn(v - __half2float(h));
    }
}

// ============================= orchestration ===============================
extern "C" void kernel_launch(void* const* d_in, const int* in_sizes, int n_in,
                              void* d_out, int out_size) {
    (void)in_sizes; (void)n_in; (void)out_size;
    const float* x = (const float*)d_in[0];
    const float* W[4] = {(const float*)d_in[1], (const float*)d_in[3],
                         (const float*)d_in[5], (const float*)d_in[7]};
    const float* bb[4] = {(const float*)d_in[2], (const float*)d_in[4],
                          (const float*)d_in[6], (const float*)d_in[8]};
    float* out = (float*)d_out;

    h16 *wh, *xth, *xtl, *p1h, *p1l, *p2h, *p2l, *sxh, *sxl, *cxh, *cxl;
    h16 *dsph, *dspl, *lsth, *lstl;
    float *dnum, *lnum, *ss, *cs;
    cudaGetSymbolAddress((void**)&wh, g_wh);
    cudaGetSymbolAddress((void**)&xth, g_xth); cudaGetSymbolAddress((void**)&xtl, g_xtl);
    cudaGetSymbolAddress((void**)&p1h, g_p1h); cudaGetSymbolAddress((void**)&p1l, g_p1l);
    cudaGetSymbolAddress((void**)&p2h, g_p2h); cudaGetSymbolAddress((void**)&p2l, g_p2l);
    cudaGetSymbolAddress((void**)&sxh, g_sxh); cudaGetSymbolAddress((void**)&sxl, g_sxl);
    cudaGetSymbolAddress((void**)&cxh, g_cxh); cudaGetSymbolAddress((void**)&cxl, g_cxl);
    cudaGetSymbolAddress((void**)&dsph, g_dsph); cudaGetSymbolAddress((void**)&dspl, g_dspl);
    cudaGetSymbolAddress((void**)&lsth, g_lsth); cudaGetSymbolAddress((void**)&lstl, g_lstl);
    cudaGetSymbolAddress((void**)&dnum, g_dnum); cudaGetSymbolAddress((void**)&lnum, g_lnum);
    cudaGetSymbolAddress((void**)&ss, g_ss);   cudaGetSymbolAddress((void**)&cs, g_cs);

    cudaFuncSetAttribute(gemm_mma<0>, cudaFuncAttributeMaxDynamicSharedMemorySize, SMEMB);
    cudaFuncSetAttribute(gemm_mma<1>, cudaFuncAttributeMaxDynamicSharedMemorySize, SMEMB);
    cudaFuncSetAttribute(gemm_mma<2>, cudaFuncAttributeMaxDynamicSharedMemorySize, SMEMB);
    cudaFuncSetAttribute(gemm_mma<3>, cudaFuncAttributeMaxDynamicSharedMemorySize, SMEMB);

    const long LD = (long)Ll * Dd;
    const long DDm = (long)Dd * Dd;
    const long LLm = (long)Ll * Ll;
    const dim3 tb(32, 8);

    // ---- input conversions (weights hi-only: they are always the B operand) ----
    for (int i = 0; i < 4; i++) {
        long n4 = 3L * Dd * Dd / 4;
        split_kernel<<<(unsigned)((n4 + 255) / 256), 256>>>(
            (const float4*)W[i],
            (__half2*)(wh + (size_t)i * 3 * Dd * Dd), nullptr, n4);
    }
    split_transpose<<<dim3(Ll / 32, Dd / 32, Bz), tb>>>(x, xth, xtl, Dd, Ll);  // x -> LD pair

    // ---- 3-layer pointwise MLP in LD layout ----
    const dim3 gM(Dd / 256, Ll / 128, Bz);
    auto mlp = [&](int wi, const float* bias, h16* oh, h16* ol) {
        const h16* wph = wh + (size_t)wi * 3 * Dd * Dd;
        gemm_mma<1><<<gM, 256, SMEMB>>>(Ll, Dd, Dd, xth, xtl, LD, wph, 0,
                                        nullptr, p1h, p1l, LD, bias, 0);
        gemm_mma<1><<<gM, 256, SMEMB>>>(Ll, Dd, Dd, p1h, p1l, LD, wph + DDm, 0,
                                        nullptr, p2h, p2l, LD, bias + Dd, 0);
        gemm_mma<1><<<gM, 256, SMEMB>>>(Ll, Dd, Dd, p2h, p2l, LD, wph + 2 * DDm, 0,
                                        nullptr, oh, ol, LD, bias + 2 * Dd, 0);
    };

    // ---------------- dscore branch ----------------
    mlp(0, bb[0], sxh, sxl);   // dsx (LD)
    mlp(1, bb[1], cxh, cxl);   // dcx (LD)
    transpose_u16<<<dim3(Dd / 32, Ll / 32, Bz), tb>>>((const unsigned short*)sxh, (unsigned short*)p1h, Ll, Dd);
    transpose_u16<<<dim3(Dd / 32, Ll / 32, Bz), tb>>>((const unsigned short*)sxl, (unsigned short*)p1l, Ll, Dd);
    transpose_u16<<<dim3(Dd / 32, Ll / 32, Bz), tb>>>((const unsigned short*)cxh, (unsigned short*)p2h, Ll, Dd);
    transpose_u16<<<dim3(Dd / 32, Ll / 32, Bz), tb>>>((const unsigned short*)cxl, (unsigned short*)p2l, Ll, Dd);
    sumsq_row_pair<<<Bz * Dd, 256>>>(p1h, p1l, ss, Ll);
    sumsq_row_pair<<<Bz * Dd, 256>>>(p2h, p2l, cs, Ll);
    // dnum = dsx_DL(pair) @ dcx_DL(hi)^T
    gemm_mma<0><<<dim3(Dd / 256, Dd / 128, Bz), 256, SMEMB>>>(Dd, Dd, Ll,
        p1h, p1l, LD, p2h, LD, dnum, nullptr, nullptr, DDm, nullptr, 0);
    cauchy_kernel<<<(unsigned)((Bz * DDm + 255) / 256), 256>>>(dnum, ss, cs, Dd);
    softmax_col_split<<<dim3(Dd / 256, 1, Bz), 256>>>(dnum, dsph, dspl, Dd);

    // ---------------- lscore branch ----------------
    mlp(2, bb[2], sxh, sxl);   // lsx (LD)
    mlp(3, bb[3], cxh, cxl);   // lcx (LD)
    sumsq_row_pair<<<Bz * Ll, 256>>>(sxh, sxl, ss, Dd);
    sumsq_row_pair<<<Bz * Ll, 256>>>(cxh, cxl, cs, Dd);
    // lnum = lsx_LD(pair) @ lcx_LD(hi)^T
    gemm_mma<0><<<dim3(Ll / 256, Ll / 128, Bz), 256, SMEMB>>>(Ll, Ll, Dd,
        sxh, sxl, LD, cxh, LD, lnum, nullptr, nullptr, LLm, nullptr, 0);
    // fused cauchy + row softmax -> h16 row-major (into lstl as temp), then transpose hi
    cauchy_softmax_row_h16<<<Bz * Ll, 256>>>(lnum, ss, cs, lstl, Ll);
    transpose_u16<<<dim3(Ll / 32, Ll / 32, Bz), tb>>>((const unsigned short*)lstl, (unsigned short*)lsth, Ll, Ll);

    // ---------------- combine ----------------
    // T[d,l] = sum_d2 dscore[d,d2](pair) * x_LD[l,d2](hi) -> pair (DL layout)
    gemm_mma<2><<<dim3(Ll / 256, Dd / 128, Bz), 256, SMEMB>>>(Dd, Ll, Dd,
        dsph, dspl, DDm, xth, LD, nullptr, p1h, p1l, LD, nullptr, 0);
    // y[d,l2] = (sum_l1 T[d,l1](pair) * lscoreT[l2,l1](hi) + x) / 2
    gemm_mma<3><<<dim3(Ll / 256, Dd / 128, Bz), 256, SMEMB>>>(Dd, Ll, Ll,
        p1h, p1l, LD, lsth, LLm, out, nullptr, nullptr, LD, x, LD);
}

// round 16
// speedup vs baseline: 4.0433x; 1.0990x over previous
#include <cuda_runtime.h>
#include <cuda_fp16.h>
#include <cstdint>
#include <math.h>

#define Bz 8
#define Dd 1024
#define Ll 2048
#define CAUCHY_E 1.0100501670841680575f
#define PI_F 3.14159265358979323846f

typedef __half h16;

// ============================ device scratch ===============================
#define LDm ((long)Ll * Dd)
#define DDm ((long)Dd * Dd)
#define LLm ((long)Ll * Ll)
__device__ __align__(16) h16 g_wh[(size_t)12 * Dd * Dd], g_wl[(size_t)12 * Dd * Dd];
__device__ __align__(16) float g_bias[12 * Dd];
__device__ __align__(16) h16 g_xth[(size_t)Bz * Ll * Dd], g_xtl[(size_t)Bz * Ll * Dd];
__device__ __align__(16) h16 g_q1h[(size_t)32 * Ll * Dd], g_q1l[(size_t)32 * Ll * Dd];
__device__ __align__(16) h16 g_q2h[(size_t)32 * Ll * Dd], g_q2l[(size_t)32 * Ll * Dd];
__device__ __align__(16) h16 g_dsph[(size_t)Bz * Dd * Dd], g_dspl[(size_t)Bz * Dd * Dd];
__device__ __align__(16) h16 g_lsth[(size_t)Bz * Ll * Ll], g_lstl[(size_t)Bz * Ll * Ll];
__device__ __align__(16) float g_dnum[(size_t)Bz * Dd * Dd];
__device__ __align__(16) float g_lnum[(size_t)Bz * Ll * Ll];
__device__ float g_ss[(size_t)Bz * Ll], g_cs[(size_t)Bz * Ll];

// ============================= mma helpers =================================
__device__ __forceinline__ void mma16816(float* c, const uint32_t* a, const uint32_t* b) {
    asm volatile(
        "mma.sync.aligned.m16n8k16.row.col.f32.f16.f16.f32 "
        "{%0,%1,%2,%3}, {%4,%5,%6,%7}, {%8,%9}, {%0,%1,%2,%3};"
        : "+f"(c[0]), "+f"(c[1]), "+f"(c[2]), "+f"(c[3])
        : "r"(a[0]), "r"(a[1]), "r"(a[2]), "r"(a[3]), "r"(b[0]), "r"(b[1]));
}
__device__ __forceinline__ void ldsm_x4(uint32_t* r, uint32_t addr) {
    asm volatile("ldmatrix.sync.aligned.m8n8.x4.shared.b16 {%0,%1,%2,%3}, [%4];"
                 : "=r"(r[0]), "=r"(r[1]), "=r"(r[2]), "=r"(r[3]) : "r"(addr));
}
__device__ __forceinline__ uint32_t smem_u32(const void* p) {
    uint32_t a;
    asm("{ .reg .u64 t; cvta.to.shared.u64 t, %1; cvt.u32.u64 %0, t; }" : "=r"(a) : "l"(p));
    return a;
}
__device__ __forceinline__ void cp_async16(uint32_t d, const void* g) {
    asm volatile("cp.async.cg.shared.global [%0], [%1], 16;" :: "r"(d), "l"(g));
}

// ===========================================================================
// 2-term split-fp16 GEMM via mma.sync: C[z] = (Ah + Al) * Bh^T  (hh + lh)
// A: MxK (K-major) hi/lo pair, B: NxK (K-major) hi only.
// CTA 128x256, 256 thr (8 warps: 2M x 4N, warp tile 64x64), K-chunk 32,
// 4-stage cp.async(.cg) pipeline, single __syncthreads per chunk.
// Rows padded 64B->80B (conflict-free ldmatrix).
// MODE 0: A,B,aux indexed by bz (aux by bz*sAux in EPI3)
// MODE 1: A by (bz&7), B,aux by (bz>>3)      [batched MLP layer 1]
// MODE 2: A by bz,    B,aux by (bz>>3)      [batched MLP layers 2,3]
// MODE 3: A by (bz>>3), B by bz, aux by (bz>>3)  [swapped d-branch layer 3]
// EPI 0: fp32   EPI 1: h16 pair + bias[col]   EPI 2: h16 pair
// EPI 3: fp32 = (acc + aux)/2                 EPI 4: h16 pair + bias[row]
// ===========================================================================
#define ROWB 80
#define ABUF 10240            // 128 rows * 80B
#define STAGEB 40960          // Ah | Al | Bh
#define NSTG 4
#define SMEMB (NSTG * STAGEB)

template <int EPI, int MODE>
__global__ void __launch_bounds__(256, 1) gemm_mma(
    int M, int N, int K,
    const h16* __restrict__ Ah, const h16* __restrict__ Al, long sA,
    const h16* __restrict__ Bh, long sB,
    float* __restrict__ C, h16* __restrict__ Ch, h16* __restrict__ Cl, long sC,
    const float* __restrict__ aux, long sAux)
{
    extern __shared__ __align__(16) char smem[];
    const uint32_t su = smem_u32(smem);
    const int tid = threadIdx.x;
    const int wid = tid >> 5, lane = tid & 31;
    const int gid = lane >> 2, tig = lane & 3;
    const int warpM = wid >> 2, warpN = wid & 3;     // 2 x 4
    const int m0 = blockIdx.y * 128, n0 = blockIdx.x * 256, bz = blockIdx.z;

    long offA;
    if (MODE == 1)      offA = (long)(bz & 7) * sA;
    else if (MODE == 3) offA = (long)(bz >> 3) * sA;
    else                offA = (long)bz * sA;
    const long offB = (MODE == 1 || MODE == 2) ? (long)(bz >> 3) * sB : (long)bz * sB;
    const h16* pAh = Ah + offA;
    const h16* pAl = Al + offA;
    const h16* pBh = Bh + offB;
    const float* auxp = (MODE != 0) ? aux + (long)(bz >> 3) * sAux : aux;

    auto issue = [&](int stage, int k0) {
        const uint32_t sb = su + stage * STAGEB;
        #pragma unroll
        for (int t = 0; t < 8; ++t) {               // 512 rows * 4 chunks / 256 thr
            int idx = tid + t * 256;
            int r = idx >> 2, ch = idx & 3;
            const h16* g;
            uint32_t dst;
            if (r < 128) {
                g = pAh + (long)(m0 + r) * K + k0 + ch * 8;
                dst = sb + r * ROWB + ch * 16;
            } else if (r < 256) {
                int rr = r - 128;
                g = pAl + (long)(m0 + rr) * K + k0 + ch * 8;
                dst = sb + ABUF + rr * ROWB + ch * 16;
            } else {
                int rr = r - 256;                   // 0..255 -> B rows
                g = pBh + (long)(n0 + rr) * K + k0 + ch * 8;
                dst = sb + 2 * ABUF + rr * ROWB + ch * 16;
            }
            cp_async16(dst, g);
        }
    };

    float acc[4][8][4];
    #pragma unroll
    for (int i = 0; i < 4; i++)
        #pragma unroll
        for (int j = 0; j < 8; j++)
            #pragma unroll
            for (int q = 0; q < 4; q++) acc[i][j][q] = 0.f;

    const int nch = K >> 5;
    issue(0, 0);
    asm volatile("cp.async.commit_group;" ::: "memory");
    if (nch > 1) issue(1, 32);
    asm volatile("cp.async.commit_group;" ::: "memory");

    const int arow = lane & 15;
    const int acolx = (lane >> 4) * 8;
    const int brow = ((lane >> 4) & 1) * 8 + (lane & 7);
    const int bkoff = ((lane >> 3) & 1) * 8;

    for (int c = 0; c < nch; ++c) {
        if (c + 2 < nch) issue((c + 2) % NSTG, (c + 2) << 5);
        asm volatile("cp.async.commit_group;" ::: "memory");
        asm volatile("cp.async.wait_group 2;" ::: "memory");
        __syncthreads();

        const uint32_t sb = su + (c % NSTG) * STAGEB;
        #pragma unroll
        for (int kk = 0; kk < 32; kk += 16) {
            uint32_t ah[4][4], al[4][4];
            #pragma unroll
            for (int mt = 0; mt < 4; ++mt) {
                uint32_t ad = sb + (warpM * 64 + mt * 16 + arow) * ROWB + (kk + acolx) * 2;
                ldsm_x4(ah[mt], ad);
                ldsm_x4(al[mt], ad + ABUF);
            }
            #pragma unroll
            for (int h = 0; h < 2; ++h) {
                uint32_t bh[4][2];
                #pragma unroll
                for (int p = 0; p < 2; ++p) {
                    uint32_t bd = sb + 2 * ABUF +
                                  (warpN * 64 + h * 32 + p * 16 + brow) * ROWB +
                                  (kk + bkoff) * 2;
                    uint32_t rh[4];
                    ldsm_x4(rh, bd);
                    bh[p * 2][0] = rh[0]; bh[p * 2][1] = rh[1];
                    bh[p * 2 + 1][0] = rh[2]; bh[p * 2 + 1][1] = rh[3];
                }
                #pragma unroll
                for (int mt = 0; mt < 4; ++mt)
                    #pragma unroll
                    for (int q = 0; q < 4; ++q) {
                        float* a = acc[mt][h * 4 + q];
                        mma16816(a, ah[mt], bh[q]);   // hh
                        mma16816(a, al[mt], bh[q]);   // lh
                    }
            }
        }
        // no trailing sync: warp skew < 1 iter; stage written at c+1 ((c+3)%4)
        // never equals the stage read at c.
    }

    // ------------------------------ epilogue ------------------------------
    #pragma unroll
    for (int mt = 0; mt < 4; ++mt) {
        const int r0 = m0 + warpM * 64 + mt * 16 + gid;
        #pragma unroll
        for (int nt = 0; nt < 8; ++nt) {
            const int cc = n0 + warpN * 64 + nt * 8 + tig * 2;
            float* a = acc[mt][nt];
            if (EPI == 0) {
                float* cp = C + (long)bz * sC;
                *(float2*)(cp + (long)r0 * N + cc)       = make_float2(a[0], a[1]);
                *(float2*)(cp + (long)(r0 + 8) * N + cc) = make_float2(a[2], a[3]);
            } else if (EPI == 1 || EPI == 2 || EPI == 4) {
                float v0 = a[0], v1 = a[1], v2 = a[2], v3 = a[3];
                if (EPI == 1) {
                    float b0 = auxp[cc], b1 = auxp[cc + 1];
                    v0 += b0; v1 += b1; v2 += b0; v3 += b1;
                }
                if (EPI == 4) {
                    float bm0 = auxp[r0], bm8 = auxp[r0 + 8];
                    v0 += bm0; v1 += bm0; v2 += bm8; v3 += bm8;
                }
                h16* hp = Ch + (long)bz * sC;
                h16* lp = Cl + (long)bz * sC;
                h16 h0 = __float2half_rn(v0), h1 = __float2half_rn(v1);
                h16 h2 = __float2half_rn(v2), h3 = __float2half_rn(v3);
                *(__half2*)(hp + (long)r0 * N + cc) = __halves2half2(h0, h1);
                *(__half2*)(hp + (long)(r0 + 8) * N + cc) = __halves2half2(h2, h3);
                *(__half2*)(lp + (long)r0 * N + cc) = __halves2half2(
                    __float2half_rn(v0 - __half2float(h0)), __float2half_rn(v1 - __half2float(h1)));
                *(__half2*)(lp + (long)(r0 + 8) * N + cc) = __halves2half2(
                    __float2half_rn(v2 - __half2float(h2)), __float2half_rn(v3 - __half2float(h3)));
            } else {   // EPI 3
                const float* xp = aux + (long)bz * sAux;
                float* cp = C + (long)bz * sC;
                float2 x0 = *(const float2*)(xp + (long)r0 * N + cc);
                float2 x1 = *(const float2*)(xp + (long)(r0 + 8) * N + cc);
                *(float2*)(cp + (long)r0 * N + cc) =
                    make_float2((a[0] + x0.x) * 0.5f, (a[1] + x0.y) * 0.5f);
                *(float2*)(cp + (long)(r0 + 8) * N + cc) =
                    make_float2((a[2] + x1.x) * 0.5f, (a[3] + x1.y) * 0.5f);
            }
        }
    }
}

// ========================= conversions / pointwise =========================
__global__ void split_kernel(const float4* __restrict__ in,
                             __half2* __restrict__ h2, __half2* __restrict__ l2, long n4) {
    long i = (long)blockIdx.x * blockDim.x + threadIdx.x;
    if (i >= n4) return;
    float4 v = in[i];
    h16 ha = __float2half_rn(v.x), hb = __float2half_rn(v.y);
    h16 hc = __float2half_rn(v.z), hd = __float2half_rn(v.w);
    h2[2 * i]     = __halves2half2(ha, hb);
    h2[2 * i + 1] = __halves2half2(hc, hd);
    l2[2 * i]     = __halves2half2(__float2half_rn(v.x - __half2float(ha)),
                                   __float2half_rn(v.y - __half2float(hb)));
    l2[2 * i + 1] = __halves2half2(__float2half_rn(v.z - __half2float(hc)),
                                   __float2half_rn(v.w - __half2float(hd)));
}

// fp32 [z][R][C] -> (hi,lo) h16 [z][C][R]
__global__ void split_transpose(const float* __restrict__ in,
                                h16* __restrict__ oh, h16* __restrict__ ol, int R, int C) {
    __shared__ float t[32][33];
    const long ob = (long)blockIdx.z * R * C;
    int r0 = blockIdx.y * 32, c0 = blockIdx.x * 32;
    int tx = threadIdx.x, ty = threadIdx.y;
    #pragma unroll
    for (int i = 0; i < 4; i++)
        t[ty + i * 8][tx] = in[ob + (long)(r0 + ty + i * 8) * C + c0 + tx];
    __syncthreads();
    #pragma unroll
    for (int i = 0; i < 4; i++) {
        int oc = c0 + ty + i * 8;
        float v = t[tx][ty + i * 8];
        h16 h = __float2half_rn(v);
        oh[ob + (long)oc * R + r0 + tx] = h;
        ol[ob + (long)oc * R + r0 + tx] = __float2half_rn(v - __half2float(h));
    }
}

// 16-bit [z][R][C] -> [z][C][R] (bit-exact move)
__global__ void transpose_u16(const unsigned short* __restrict__ in,
                              unsigned short* __restrict__ out, int R, int C) {
    __shared__ unsigned short t[32][34];
    const long ob = (long)blockIdx.z * R * C;
    int r0 = blockIdx.y * 32, c0 = blockIdx.x * 32;
    int tx = threadIdx.x, ty = threadIdx.y;
    #pragma unroll
    for (int i = 0; i < 4; i++)
        t[ty + i * 8][tx] = in[ob + (long)(r0 + ty + i * 8) * C + c0 + tx];
    __syncthreads();
    #pragma unroll
    for (int i = 0; i < 4; i++)
        out[ob + (long)(c0 + ty + i * 8) * R + r0 + tx] = t[tx][ty + i * 8];
}

__device__ __forceinline__ float blockReduceSum(float v) {
    __shared__ float sm[32];
    __syncthreads();
    int lane = threadIdx.x & 31, w = threadIdx.x >> 5;
    #pragma unroll
    for (int o = 16; o; o >>= 1) v += __shfl_down_sync(0xffffffffu, v, o);
    if (!lane) sm[w] = v;
    __syncthreads();
    int nw = blockDim.x >> 5;
    v = (threadIdx.x < nw) ? sm[threadIdx.x] : 0.f;
    if (w == 0) {
        #pragma unroll
        for (int o = 16; o; o >>= 1) v += __shfl_down_sync(0xffffffffu, v, o);
        if (!lane) sm[0] = v;
    }
    __syncthreads();
    return sm[0];
}
__device__ __forceinline__ float blockReduceMax(float v) {
    __shared__ float sm[32];
    __syncthreads();
    int lane = threadIdx.x & 31, w = threadIdx.x >> 5;
    #pragma unroll
    for (int o = 16; o; o >>= 1) v = fmaxf(v, __shfl_down_sync(0xffffffffu, v, o));
    if (!lane) sm[w] = v;
    __syncthreads();
    int nw = blockDim.x >> 5;
    v = (threadIdx.x < nw) ? sm[threadIdx.x] : -1e30f;
    if (w == 0) {
        #pragma unroll
        for (int o = 16; o; o >>= 1) v = fmaxf(v, __shfl_down_sync(0xffffffffu, v, o));
        if (!lane) sm[0] = v;
    }
    __syncthreads();
    return sm[0];
}

// per-row sum of (hi+lo)^2, contiguous length C; one block per row
__global__ void sumsq_row_pair(const h16* __restrict__ h, const h16* __restrict__ l,
                               float* __restrict__ out, int C) {
    long row = blockIdx.x;
    const h16* hp = h + row * (long)C;
    const h16* lp = l + row * (long)C;
    float s = 0.f;
    for (int i = threadIdx.x; i < C; i += blockDim.x) {
        float v = __half2float(hp[i]) + __half2float(lp[i]);
        s = fmaf(v, v, s);
    }
    s = blockReduceSum(s);
    if (threadIdx.x == 0) out[row] = s;
}

// fused: lscore row = softmax(relu(cauchy(lnum row))) -> h16 row-major
__global__ void cauchy_softmax_row_h16(const float* __restrict__ S,
                                       const float* __restrict__ ss,
                                       const float* __restrict__ cs,
                                       h16* __restrict__ outh, int M) {
    const long row = blockIdx.x;
    const int b = (int)(row / M), r = (int)(row % M);
    const float* p = S + row * (long)M;
    const float ssr = ss[(long)b * M + r];
    const float* csb = cs + (long)b * M;
    float v[8];
    float mx = -1e30f;
    #pragma unroll
    for (int i = 0; i < 8; i++) {
        int cidx = threadIdx.x + i * 256;
        float mm = p[cidx];
        float q = (mm * mm) / (ssr * csb[cidx]);
        float pw = __powf(q, CAUCHY_E);
        if (cidx == r) pw -= 1.0f;
        float o = 0.5f - 0.5f * __cosf(pw * PI_F);
        o = fmaxf(o, 0.0f);
        v[i] = o;
        mx = fmaxf(mx, o);
    }
    mx = blockReduceMax(mx);
    float s = 0.f;
    #pragma unroll
    for (int i = 0; i < 8; i++) { v[i] = __expf(v[i] - mx); s += v[i]; }
    s = blockReduceSum(s);
    float inv = 1.0f / s;
    #pragma unroll
    for (int i = 0; i < 8; i++)
        outh[row * (long)M + threadIdx.x + i * 256] = __float2half_rn(v[i] * inv);
}

__global__ void cauchy_kernel(float* __restrict__ S, const float* __restrict__ ss,
                              const float* __restrict__ cs, int M) {
    long idx = (long)blockIdx.x * blockDim.x + threadIdx.x;
    long total = (long)Bz * M * M;
    if (idx >= total) return;
    int c = (int)(idx % M);
    int r = (int)((idx / M) % M);
    int b = (int)(idx / ((long)M * M));
    float mm = S[idx];
    float v = (mm * mm) / (ss[(long)b * M + r] * cs[(long)b * M + c]);
    float p = __powf(v, CAUCHY_E);
    if (r == c) p -= 1.0f;
    float o = 0.5f - 0.5f * __cosf(p * PI_F);
    S[idx] = fmaxf(o, 0.0f);
}

// softmax over axis 1 of (B, M, M), thread per column; final pass writes h16 pair
__global__ void softmax_col_split(float* __restrict__ S,
                                  h16* __restrict__ hp, h16* __restrict__ lp, int M) {
    int n = blockIdx.x * blockDim.x + threadIdx.x;
    int b = blockIdx.z;
    const long ob = (long)b * M * M;
    float* base = S + ob + n;
    float mx = -1e30f;
    for (int m = 0; m < M; m++) mx = fmaxf(mx, base[(long)m * M]);
    float s = 0.f;
    for (int m = 0; m < M; m++) {
        float e = __expf(base[(long)m * M] - mx);
        base[(long)m * M] = e;
        s += e;
    }
    float inv = 1.0f / s;
    for (int m = 0; m < M; m++) {
        float v = base[(long)m * M] * inv;
        h16 h = __float2half_rn(v);
        hp[ob + (long)m * M + n] = h;
        lp[ob + (long)m * M + n] = __float2half_rn(v - __half2float(h));
    }
}

// ============================= orchestration ===============================
extern "C" void kernel_launch(void* const* d_in, const int* in_sizes, int n_in,
                              void* d_out, int out_size) {
    (void)in_sizes; (void)n_in; (void)out_size;
    const float* x = (const float*)d_in[0];
    const float* W[4] = {(const float*)d_in[1], (const float*)d_in[3],
                         (const float*)d_in[5], (const float*)d_in[7]};
    const float* bb[4] = {(const float*)d_in[2], (const float*)d_in[4],
                          (const float*)d_in[6], (const float*)d_in[8]};
    float* out = (float*)d_out;

    h16 *wh, *wl, *xth, *xtl, *q1h, *q1l, *q2h, *q2l, *dsph, *dspl, *lsth, *lstl;
    float *bias, *dnum, *lnum, *ss, *cs;
    cudaGetSymbolAddress((void**)&wh, g_wh);   cudaGetSymbolAddress((void**)&wl, g_wl);
    cudaGetSymbolAddress((void**)&bias, g_bias);
    cudaGetSymbolAddress((void**)&xth, g_xth); cudaGetSymbolAddress((void**)&xtl, g_xtl);
    cudaGetSymbolAddress((void**)&q1h, g_q1h); cudaGetSymbolAddress((void**)&q1l, g_q1l);
    cudaGetSymbolAddress((void**)&q2h, g_q2h); cudaGetSymbolAddress((void**)&q2l, g_q2l);
    cudaGetSymbolAddress((void**)&dsph, g_dsph); cudaGetSymbolAddress((void**)&dspl, g_dspl);
    cudaGetSymbolAddress((void**)&lsth, g_lsth); cudaGetSymbolAddress((void**)&lstl, g_lstl);
    cudaGetSymbolAddress((void**)&dnum, g_dnum); cudaGetSymbolAddress((void**)&lnum, g_lnum);
    cudaGetSymbolAddress((void**)&ss, g_ss);   cudaGetSymbolAddress((void**)&cs, g_cs);

    cudaFuncSetAttribute(gemm_mma<1, 1>, cudaFuncAttributeMaxDynamicSharedMemorySize, SMEMB);
    cudaFuncSetAttribute(gemm_mma<1, 2>, cudaFuncAttributeMaxDynamicSharedMemorySize, SMEMB);
    cudaFuncSetAttribute(gemm_mma<4, 3>, cudaFuncAttributeMaxDynamicSharedMemorySize, SMEMB);
    cudaFuncSetAttribute(gemm_mma<0, 0>, cudaFuncAttributeMaxDynamicSharedMemorySize, SMEMB);
    cudaFuncSetAttribute(gemm_mma<2, 0>, cudaFuncAttributeMaxDynamicSharedMemorySize, SMEMB);
    cudaFuncSetAttribute(gemm_mma<3, 0>, cudaFuncAttributeMaxDynamicSharedMemorySize, SMEMB);

    const dim3 tb(32, 8);

    // ---- input conversions ----
    for (int i = 0; i < 4; i++) {
        long n4 = 3L * Dd * Dd / 4;
        split_kernel<<<(unsigned)((n4 + 255) / 256), 256>>>(
            (const float4*)W[i],
            (__half2*)(wh + (size_t)i * 3 * Dd * Dd),
            (__half2*)(wl + (size_t)i * 3 * Dd * Dd), n4);
        cudaMemcpyAsync(bias + (size_t)i * 3 * Dd, bb[i], 3 * Dd * sizeof(float),
                        cudaMemcpyDeviceToDevice);
    }
    split_transpose<<<dim3(Ll / 32, Dd / 32, Bz), tb>>>(x, xth, xtl, Dd, Ll);  // x -> LD pair

    // ---- all 4 MLPs batched over z = mlp*8 + b ----
    // L1: q1[z] = x[b] @ W[mlp][0]^T + bias   (z = 0..31)
    gemm_mma<1, 1><<<dim3(Dd / 256, Ll / 128, 32), 256, SMEMB>>>(Ll, Dd, Dd,
        xth, xtl, LDm, wh, 3 * DDm, nullptr, q1h, q1l, LDm, bias, 3 * Dd);
    // L2: q2[z] = q1[z] @ W[mlp][1]^T + bias
    gemm_mma<1, 2><<<dim3(Dd / 256, Ll / 128, 32), 256, SMEMB>>>(Ll, Dd, Dd,
        q1h, q1l, LDm, wh + DDm, 3 * DDm, nullptr, q2h, q2l, LDm, bias + Dd, 3 * Dd);
    // L3 l-branch (mlps 2,3 -> z=16..31 of q2): normal orientation, LD output
    gemm_mma<1, 2><<<dim3(Dd / 256, Ll / 128, 16), 256, SMEMB>>>(Ll, Dd, Dd,
        q2h + 16 * LDm, q2l + 16 * LDm, LDm, wh + 2 * 3 * DDm + 2 * DDm, 3 * DDm,
        nullptr, q1h + 16 * LDm, q1l + 16 * LDm, LDm, bias + 2 * 3 * Dd + 2 * Dd, 3 * Dd);
    // L3 d-branch (mlps 0,1 -> z=0..15): swapped -> DL output directly
    gemm_mma<4, 3><<<dim3(Ll / 256, Dd / 128, 16), 256, SMEMB>>>(Dd, Ll, Dd,
        wh + 2 * DDm, wl + 2 * DDm, 3 * DDm, q2h, LDm,
        nullptr, q1h, q1l, LDm, bias + 2 * Dd, 3 * Dd);

    // ---------------- dscore branch (dsx = q1 z0..7 DL, dcx = z8..15 DL) ----
    sumsq_row_pair<<<Bz * Dd, 256>>>(q1h, q1l, ss, Ll);
    sumsq_row_pair<<<Bz * Dd, 256>>>(q1h + 8 * LDm, q1l + 8 * LDm, cs, Ll);
    gemm_mma<0, 0><<<dim3(Dd / 256, Dd / 128, Bz), 256, SMEMB>>>(Dd, Dd, Ll,
        q1h, q1l, LDm, q1h + 8 * LDm, LDm, dnum, nullptr, nullptr, DDm, nullptr, 0);
    cauchy_kernel<<<(unsigned)((Bz * DDm + 255) / 256), 256>>>(dnum, ss, cs, Dd);
    softmax_col_split<<<dim3(Dd / 256, 1, Bz), 256>>>(dnum, dsph, dspl, Dd);

    // ---------------- lscore branch (lsx = q1 z16..23 LD, lcx = z24..31) ----
    sumsq_row_pair<<<Bz * Ll, 256>>>(q1h + 16 * LDm, q1l + 16 * LDm, ss, Dd);
    sumsq_row_pair<<<Bz * Ll, 256>>>(q1h + 24 * LDm, q1l + 24 * LDm, cs, Dd);
    gemm_mma<0, 0><<<dim3(Ll / 256, Ll / 128, Bz), 256, SMEMB>>>(Ll, Ll, Dd,
        q1h + 16 * LDm, q1l + 16 * LDm, LDm, q1h + 24 * LDm, LDm,
        lnum, nullptr, nullptr, LLm, nullptr, 0);
    cauchy_softmax_row_h16<<<Bz * Ll, 256>>>(lnum, ss, cs, lstl, Ll);
    transpose_u16<<<dim3(Ll / 32, Ll / 32, Bz), tb>>>(
        (const unsigned short*)lstl, (unsigned short*)lsth, Ll, Ll);

    // ---------------- combine ----------------
    // T[d,l] = dscore(pair) @ x_LD(hi)^T -> pair (DL) into q2 z0..7
    gemm_mma<2, 0><<<dim3(Ll / 256, Dd / 128, Bz), 256, SMEMB>>>(Dd, Ll, Dd,
        dsph, dspl, DDm, xth, LDm, nullptr, q2h, q2l, LDm, nullptr, 0);
    // y = (T(pair) @ lscoreT(hi)^T + x) / 2
    gemm_mma<3, 0><<<dim3(Ll / 256, Dd / 128, Bz), 256, SMEMB>>>(Dd, Ll, Ll,
        q2h, q2l, LDm, lsth, LLm, out, nullptr, nullptr, LDm, x, LDm);
}